// round 11
// baseline (speedup 1.0000x reference)
#include <cuda_runtime.h>
#include <cuda_fp16.h>
#include <cstdint>
#include <cstring>

#define NN 50000
#define EE 800000
#define FD 256          // H*HID
#define NEG 0.2f
#define NB 49           // ceil(NN/1024)

__device__ __forceinline__ uint32_t h2_as_u32(__half2 v) {
    uint32_t u;
    memcpy(&u, &v, 4);
    return u;
}

// ---------------- side stream (created pre-main; streams are not device mem) --
static cudaStream_t g_s2 = nullptr;
static cudaEvent_t  g_evFork = nullptr, g_evJoin = nullptr;
namespace {
struct StreamInit {
    StreamInit() {
        if (cudaStreamCreateWithFlags(&g_s2, cudaStreamNonBlocking) != cudaSuccess)
            g_s2 = nullptr;
        if (cudaEventCreateWithFlags(&g_evFork, cudaEventDisableTiming) != cudaSuccess)
            g_evFork = nullptr;
        if (cudaEventCreateWithFlags(&g_evJoin, cudaEventDisableTiming) != cudaSuccess)
            g_evJoin = nullptr;
    }
};
static StreamInit g_streamInit;
}

// ---------------- scratch (device globals; no allocation allowed) ------------
__device__ __half g_feath[(size_t)NN * FD];   // fp16 post-GEMM features
__device__ __half g_xh[(size_t)NN * 128];     // fp16 input x
__device__ __half g_hAh[(size_t)NN * FD];     // fp16 h ping
__device__ __half g_hBh[(size_t)NN * FD];     // fp16 h pong
__device__ __half g_W1h[256 * 128];
__device__ __half g_W2h[256 * 256];
__device__ __half g_W3h[256 * 256];
__device__ float g_el[NN * 4];
__device__ float g_er[NN * 4];
__device__ float g_f4[NN * 8];
__device__ float g_r4[NN * 8];
__device__ int   g_cnt[NN];
__device__ int   g_rowptr[NN + 1];
__device__ int   g_cur[NN];
__device__ int   g_csrc[EE];
__device__ int   g_bsum[64];
__device__ int   g_tick;

// ---------------- merged fp32 -> fp16 converts (x + W1..W3) ------------------
__global__ void k_cvtAll(const float4* __restrict__ x, uint2* __restrict__ xo, int xn4,
                         const float4* __restrict__ w1, uint2* __restrict__ o1,
                         const float4* __restrict__ w2, uint2* __restrict__ o2,
                         const float4* __restrict__ w3, uint2* __restrict__ o3) {
    int i = blockIdx.x * blockDim.x + threadIdx.x;
    if (i < xn4) {
        float4 v = x[i];
        xo[i] = make_uint2(h2_as_u32(__floats2half2_rn(v.x, v.y)),
                           h2_as_u32(__floats2half2_rn(v.z, v.w)));
    }
    if (i < 8192) {
        float4 v = w1[i];
        o1[i] = make_uint2(h2_as_u32(__floats2half2_rn(v.x, v.y)),
                           h2_as_u32(__floats2half2_rn(v.z, v.w)));
    }
    if (i < 16384) {
        float4 v = w2[i];
        o2[i] = make_uint2(h2_as_u32(__floats2half2_rn(v.x, v.y)),
                           h2_as_u32(__floats2half2_rn(v.z, v.w)));
        float4 u = w3[i];
        o3[i] = make_uint2(h2_as_u32(__floats2half2_rn(u.x, u.y)),
                           h2_as_u32(__floats2half2_rn(u.z, u.w)));
    }
}

// ---------------- CSR build --------------------------------------------------
__global__ void k_zero_cnt(int* cnt) {
    int i = blockIdx.x * blockDim.x + threadIdx.x;
    if (i < NN) cnt[i] = 0;
}

__global__ void k_histo(const int* __restrict__ dst, int* __restrict__ cnt, int E) {
    for (int i = blockIdx.x * blockDim.x + threadIdx.x; i < E; i += gridDim.x * blockDim.x)
        atomicAdd(&cnt[dst[i]], 1);
}

// block sums + (last block) tiny scan of block sums, fused via ticket
__global__ void k_scan_part_fused(const int* __restrict__ cnt, int* __restrict__ rowptr) {
    __shared__ int sh[1024];
    __shared__ bool isLast;
    int tid = threadIdx.x;
    int i = blockIdx.x * 1024 + tid;
    sh[tid] = (i < NN) ? cnt[i] : 0;
    __syncthreads();
    for (int o = 512; o > 0; o >>= 1) {
        if (tid < o) sh[tid] += sh[tid + o];
        __syncthreads();
    }
    if (tid == 0) {
        g_bsum[blockIdx.x] = sh[0];
        __threadfence();
        int t = atomicAdd(&g_tick, 1);
        isLast = (t == gridDim.x - 1);
    }
    __syncthreads();
    if (isLast) {
        int v = 0;
        if (tid < 64) {
            v = (tid < NB) ? *((volatile int*)&g_bsum[tid]) : 0;
            sh[tid] = v;
        }
        __syncthreads();
        #pragma unroll
        for (int o = 1; o < 64; o <<= 1) {
            int u = (tid >= o && tid < 64) ? sh[tid - o] : 0;
            __syncthreads();
            if (tid < 64) sh[tid] += u;
            __syncthreads();
        }
        if (tid < NB) g_bsum[tid] = sh[tid] - v;   // exclusive prefix
        if (tid == 63) rowptr[NN] = sh[63];
        if (tid == 0) g_tick = 0;                  // reset for next call
    }
}

__global__ void k_scan_final(const int* __restrict__ cnt, int* __restrict__ rowptr,
                             int* __restrict__ cur) {
    __shared__ int sh[1024];
    int tid = threadIdx.x;
    int i = blockIdx.x * 1024 + tid;
    int v = (i < NN) ? cnt[i] : 0;
    sh[tid] = v;
    __syncthreads();
    #pragma unroll
    for (int o = 1; o < 1024; o <<= 1) {
        int t = (tid >= o) ? sh[tid - o] : 0;
        __syncthreads();
        sh[tid] += t;
        __syncthreads();
    }
    if (i < NN) { int ex = g_bsum[blockIdx.x] + sh[tid] - v; rowptr[i] = ex; cur[i] = ex; }
}

__global__ void k_scatter(const int* __restrict__ src, const int* __restrict__ dst,
                          int* __restrict__ cur, int* __restrict__ csrc, int E) {
    for (int i = blockIdx.x * blockDim.x + threadIdx.x; i < E; i += gridDim.x * blockDim.x) {
        int d = dst[i];
        int p = atomicAdd(&cur[d], 1);
        csrc[p] = src[i];
    }
}

// ---------------- fp16 GEMM BN=128 (cp.async dbuf) + fused el/er -------------
#define BM 128
#define BN 128
#define BKB 64                    // fp16 k per stage
#define BKBP 72                   // +8 pad
#define ASZB (BM * BKBP)
#define BSZB (BN * BKBP)
#define GEMM_SMEM ((2 * (ASZB + BSZB)) * (int)sizeof(__half))   // 73728 B

__device__ __forceinline__ void cp16(uint32_t s, const void* g) {
    asm volatile("cp.async.cg.shared.global [%0], [%1], 16;" :: "r"(s), "l"(g));
}

__device__ __forceinline__ void mma_fp16(float (&d)[4], const uint32_t (&a)[4],
                                         const uint32_t (&b)[2]) {
    asm volatile(
        "mma.sync.aligned.m16n8k16.row.col.f32.f16.f16.f32 "
        "{%0,%1,%2,%3},{%4,%5,%6,%7},{%8,%9},{%0,%1,%2,%3};"
        : "+f"(d[0]), "+f"(d[1]), "+f"(d[2]), "+f"(d[3])
        : "r"(a[0]), "r"(a[1]), "r"(a[2]), "r"(a[3]), "r"(b[0]), "r"(b[1]));
}

__global__ void __launch_bounds__(256) k_gemm_fp16(
        const __half* __restrict__ A, const __half* __restrict__ B,
        __half* __restrict__ C,
        const float* __restrict__ al, const float* __restrict__ ar,
        float* __restrict__ el, float* __restrict__ er, int M, int K) {
    extern __shared__ __half smem[];
    __half* Asm = smem;                 // [2][BM][BKBP]
    __half* Bsm = smem + 2 * ASZB;      // [2][BN][BKBP]
    __shared__ float sAl[BN], sAr[BN];

    const int bx = blockIdx.x;
    const int bm = blockIdx.y * BM, bn = bx * BN;
    const int tid = threadIdx.x;
    const int warp = tid >> 5, lane = tid & 31;
    const int wm = warp & 3, wn = warp >> 2;      // wn in {0,1}: head within block
    const int r = lane >> 2, c = lane & 3;
    const int hg = bx * 2 + wn;

    if (tid < BN) { sAl[tid] = al[bn + tid]; sAr[tid] = ar[bn + tid]; }

    const int lrow = tid >> 1, lcol = (tid & 1) * 32;
    const bool aok = (bm + lrow) < M;

    float acc[2][8][4];
    #pragma unroll
    for (int mt = 0; mt < 2; mt++)
        #pragma unroll
        for (int nt = 0; nt < 8; nt++)
            #pragma unroll
            for (int i = 0; i < 4; i++) acc[mt][nt][i] = 0.f;

    const int ntile = K / BKB;

    auto issue = [&](int buf, int kt) {
        if (aok) {
            uint32_t sa = (uint32_t)__cvta_generic_to_shared(
                &Asm[(buf * BM + lrow) * BKBP + lcol]);
            const __half* ga = &A[(size_t)(bm + lrow) * K + kt + lcol];
            #pragma unroll
            for (int j = 0; j < 4; j++) cp16(sa + j * 16, ga + j * 8);
        }
        uint32_t sb = (uint32_t)__cvta_generic_to_shared(
            &Bsm[(buf * BN + lrow) * BKBP + lcol]);
        const __half* gb = &B[(size_t)(bn + lrow) * K + kt + lcol];
        #pragma unroll
        for (int j = 0; j < 4; j++) cp16(sb + j * 16, gb + j * 8);
    };

    issue(0, 0);
    asm volatile("cp.async.commit_group;");

    for (int t = 0; t < ntile; t++) {
        if (t + 1 < ntile) {
            issue((t + 1) & 1, (t + 1) * BKB);
            asm volatile("cp.async.commit_group;");
            asm volatile("cp.async.wait_group 1;");
        } else {
            asm volatile("cp.async.wait_group 0;");
        }
        __syncthreads();
        const __half* Ab = &Asm[((t & 1) * BM) * BKBP];
        const __half* Bb = &Bsm[((t & 1) * BN) * BKBP];
        #pragma unroll
        for (int kk = 0; kk < BKB; kk += 16) {
            uint32_t af[2][4], bf[8][2];
            #pragma unroll
            for (int mt = 0; mt < 2; mt++) {
                int row0 = wm * 32 + mt * 16 + r;
                af[mt][0] = *(const uint32_t*)&Ab[row0 * BKBP + kk + 2 * c];
                af[mt][1] = *(const uint32_t*)&Ab[(row0 + 8) * BKBP + kk + 2 * c];
                af[mt][2] = *(const uint32_t*)&Ab[row0 * BKBP + kk + 2 * c + 8];
                af[mt][3] = *(const uint32_t*)&Ab[(row0 + 8) * BKBP + kk + 2 * c + 8];
            }
            #pragma unroll
            for (int nt = 0; nt < 8; nt++) {
                int col0 = wn * 64 + nt * 8 + r;
                bf[nt][0] = *(const uint32_t*)&Bb[col0 * BKBP + kk + 2 * c];
                bf[nt][1] = *(const uint32_t*)&Bb[col0 * BKBP + kk + 2 * c + 8];
            }
            #pragma unroll
            for (int mt = 0; mt < 2; mt++)
                #pragma unroll
                for (int nt = 0; nt < 8; nt++)
                    mma_fp16(acc[mt][nt], af[mt], bf[nt]);
        }
        __syncthreads();
    }

    // ---- store fp16 feat ----
    #pragma unroll
    for (int mt = 0; mt < 2; mt++) {
        #pragma unroll
        for (int nt = 0; nt < 8; nt++) {
            int row = bm + wm * 32 + mt * 16 + r;
            int col = bn + wn * 64 + nt * 8 + 2 * c;
            if (row < M)
                *(__half2*)&C[(size_t)row * FD + col] =
                    __floats2half2_rn(acc[mt][nt][0], acc[mt][nt][1]);
            if (row + 8 < M)
                *(__half2*)&C[(size_t)(row + 8) * FD + col] =
                    __floats2half2_rn(acc[mt][nt][2], acc[mt][nt][3]);
        }
    }

    // ---- fused el/er: warp owns (rows wm*32..+31, head hg); direct write ----
    #pragma unroll
    for (int mt = 0; mt < 2; mt++) {
        #pragma unroll
        for (int rh = 0; rh < 2; rh++) {
            float se = 0.f, sr2 = 0.f;
            #pragma unroll
            for (int nt = 0; nt < 8; nt++) {
                int col = wn * 64 + nt * 8 + 2 * c;
                float a0 = acc[mt][nt][rh * 2], a1 = acc[mt][nt][rh * 2 + 1];
                se  += a0 * sAl[col] + a1 * sAl[col + 1];
                sr2 += a0 * sAr[col] + a1 * sAr[col + 1];
            }
            se  += __shfl_xor_sync(0xffffffffu, se, 1);
            se  += __shfl_xor_sync(0xffffffffu, se, 2);
            sr2 += __shfl_xor_sync(0xffffffffu, sr2, 1);
            sr2 += __shfl_xor_sync(0xffffffffu, sr2, 2);
            if (c == 0) {
                int row = bm + wm * 32 + mt * 16 + rh * 8 + r;
                if (row < M) {
                    el[row * 4 + hg] = se;
                    er[row * 4 + hg] = sr2;
                }
            }
        }
    }
}

// ---------------- fused edge aggregation: warp per node, fp16 everywhere -----
__global__ void __launch_bounds__(128) k_edge_agg(
        const uint4* __restrict__ feath,      // [N][32] x (8 fp16)
        const float4* __restrict__ el4, const float4* __restrict__ er4,
        const int* __restrict__ rowptr, const int* __restrict__ csrc,
        const uint4* __restrict__ hprevh,     // fp16 prev h or null
        const float4* __restrict__ bias4,
        uint4* __restrict__ houth) {          // fp16 out h
    int w = threadIdx.x >> 5;
    int n = blockIdx.x * 4 + w;
    int lane = threadIdx.x & 31;
    if (n >= NN) return;
    int head = lane >> 3;
    __shared__ int   ssrc[4][32];
    __shared__ float sw[4][32][4];
    int beg = rowptr[n], end = rowptr[n + 1];
    float4 erd = er4[n];
    float acc[8];
    #pragma unroll
    for (int i = 0; i < 8; i++) acc[i] = 0.f;
    float4 dl = make_float4(0.f, 0.f, 0.f, 0.f);

    #define ACCUM(fv, wgt) do {                                             \
        const __half2* _p = (const __half2*)&(fv);                          \
        _Pragma("unroll")                                                   \
        for (int _j = 0; _j < 4; _j++) {                                    \
            float2 _v = __half22float2(_p[_j]);                             \
            acc[2 * _j]     = fmaf(_v.x, (wgt), acc[2 * _j]);               \
            acc[2 * _j + 1] = fmaf(_v.y, (wgt), acc[2 * _j + 1]);           \
        } } while (0)

    for (int base = beg; base < end; base += 32) {
        int cnt = min(32, end - base);
        if (lane < cnt) {
            int s = csrc[base + lane];
            ssrc[w][lane] = s;
            float4 le = el4[s];
            float x0 = le.x + erd.x; x0 = x0 > 0.f ? x0 : NEG * x0;
            float x1 = le.y + erd.y; x1 = x1 > 0.f ? x1 : NEG * x1;
            float x2 = le.z + erd.z; x2 = x2 > 0.f ? x2 : NEG * x2;
            float x3 = le.w + erd.w; x3 = x3 > 0.f ? x3 : NEG * x3;
            float w0 = expf(x0), w1 = expf(x1), w2 = expf(x2), w3 = expf(x3);
            sw[w][lane][0] = w0; sw[w][lane][1] = w1;
            sw[w][lane][2] = w2; sw[w][lane][3] = w3;
            dl.x += w0; dl.y += w1; dl.z += w2; dl.w += w3;
        }
        __syncwarp();
        int e = 0;
        for (; e + 4 <= cnt; e += 4) {
            uint4 f0 = feath[(size_t)ssrc[w][e]     * 32 + lane];
            uint4 f1 = feath[(size_t)ssrc[w][e + 1] * 32 + lane];
            uint4 f2 = feath[(size_t)ssrc[w][e + 2] * 32 + lane];
            uint4 f3 = feath[(size_t)ssrc[w][e + 3] * 32 + lane];
            float w0 = sw[w][e][head],     w1 = sw[w][e + 1][head];
            float w2 = sw[w][e + 2][head], w3 = sw[w][e + 3][head];
            ACCUM(f0, w0); ACCUM(f1, w1); ACCUM(f2, w2); ACCUM(f3, w3);
        }
        for (; e < cnt; e++) {
            uint4 fv = feath[(size_t)ssrc[w][e] * 32 + lane];
            float wg = sw[w][e][head];
            ACCUM(fv, wg);
        }
        __syncwarp();
    }
    #undef ACCUM

    #pragma unroll
    for (int o = 16; o > 0; o >>= 1) {
        dl.x += __shfl_xor_sync(0xffffffffu, dl.x, o);
        dl.y += __shfl_xor_sync(0xffffffffu, dl.y, o);
        dl.z += __shfl_xor_sync(0xffffffffu, dl.z, o);
        dl.w += __shfl_xor_sync(0xffffffffu, dl.w, o);
    }
    float den = (head == 0) ? dl.x : (head == 1) ? dl.y : (head == 2) ? dl.z : dl.w;
    float inv = (end > beg) ? 1.f / den : 0.f;
    float4 b0 = bias4[lane * 2], b1 = bias4[lane * 2 + 1];
    float v[8];
    v[0] = acc[0] * inv + b0.x; v[1] = acc[1] * inv + b0.y;
    v[2] = acc[2] * inv + b0.z; v[3] = acc[3] * inv + b0.w;
    v[4] = acc[4] * inv + b1.x; v[5] = acc[5] * inv + b1.y;
    v[6] = acc[6] * inv + b1.z; v[7] = acc[7] * inv + b1.w;
    if (hprevh) {
        uint4 pv = hprevh[(size_t)n * 32 + lane];
        const __half2* pp = (const __half2*)&pv;
        #pragma unroll
        for (int j = 0; j < 4; j++) {
            float2 p = __half22float2(pp[j]);
            v[2 * j]     += p.x;
            v[2 * j + 1] += p.y;
        }
    }
    #pragma unroll
    for (int j = 0; j < 8; j++)
        v[j] = v[j] > 0.f ? v[j] : expm1f(v[j]);
    uint4 ob;
    ob.x = h2_as_u32(__floats2half2_rn(v[0], v[1]));
    ob.y = h2_as_u32(__floats2half2_rn(v[2], v[3]));
    ob.z = h2_as_u32(__floats2half2_rn(v[4], v[5]));
    ob.w = h2_as_u32(__floats2half2_rn(v[6], v[7]));
    houth[(size_t)n * 32 + lane] = ob;
}

// ---------------- layer-4 projection + el/er (merged, fp16 h) ----------------
__global__ void k_l4_proj(const __half* __restrict__ h, const float* __restrict__ W4,
                          const float* __restrict__ rW4,
                          const float* __restrict__ al4, const float* __restrict__ ar4,
                          float* __restrict__ f4, float* __restrict__ r4,
                          float* __restrict__ el, float* __restrict__ er) {
    int n = blockIdx.x * 8 + (threadIdx.x >> 5);
    int lane = threadIdx.x & 31;
    if (n >= NN) return;
    float acc[16];
    #pragma unroll
    for (int o = 0; o < 16; o++) acc[o] = 0.f;
    const __half* hr = h + (size_t)n * FD;
    #pragma unroll
    for (int k8 = 0; k8 < 8; k8++) {
        int k = k8 * 32 + lane;
        float hv = __half2float(hr[k]);
        #pragma unroll
        for (int o = 0; o < 8; o++) acc[o]     = fmaf(hv, W4[o * FD + k], acc[o]);
        #pragma unroll
        for (int o = 0; o < 8; o++) acc[8 + o] = fmaf(hv, rW4[o * FD + k], acc[8 + o]);
    }
    #pragma unroll
    for (int o = 0; o < 16; o++)
        #pragma unroll
        for (int off = 16; off > 0; off >>= 1)
            acc[o] += __shfl_xor_sync(0xffffffffu, acc[o], off);
    if (lane < 8) {
        f4[n * 8 + lane] = acc[lane];
        r4[n * 8 + lane] = acc[8 + lane];
    }
    if (lane < 4) {
        el[n * 4 + lane] = acc[2 * lane] * al4[2 * lane] +
                           acc[2 * lane + 1] * al4[2 * lane + 1];
        er[n * 4 + lane] = acc[2 * lane] * ar4[2 * lane] +
                           acc[2 * lane + 1] * ar4[2 * lane + 1];
    }
}

// ---------------- layer-4 edge agg + softmax + head-mean ---------------------
__global__ void k_l4_edge(const float* __restrict__ f4, const float* __restrict__ el,
                          const float* __restrict__ er, const int* __restrict__ rowptr,
                          const int* __restrict__ csrc, const float* __restrict__ r4,
                          const float* __restrict__ b4, float* __restrict__ out) {
    int n = blockIdx.x * 8 + (threadIdx.x >> 5);
    int lane = threadIdx.x & 31;
    if (n >= NN) return;
    int beg = rowptr[n], end = rowptr[n + 1];
    float4 erd = ((const float4*)er)[n];
    float acc[8] = {0, 0, 0, 0, 0, 0, 0, 0};
    float den[4] = {0, 0, 0, 0};
    for (int e = beg + lane; e < end; e += 32) {
        int s = csrc[e];
        float4 le = ((const float4*)el)[s];
        float x0 = le.x + erd.x; x0 = x0 > 0.f ? x0 : NEG * x0;
        float x1 = le.y + erd.y; x1 = x1 > 0.f ? x1 : NEG * x1;
        float x2 = le.z + erd.z; x2 = x2 > 0.f ? x2 : NEG * x2;
        float x3 = le.w + erd.w; x3 = x3 > 0.f ? x3 : NEG * x3;
        float w0 = expf(x0), w1 = expf(x1), w2 = expf(x2), w3 = expf(x3);
        den[0] += w0; den[1] += w1; den[2] += w2; den[3] += w3;
        float4 f0 = ((const float4*)f4)[s * 2];
        float4 f1 = ((const float4*)f4)[s * 2 + 1];
        acc[0] = fmaf(f0.x, w0, acc[0]);  acc[1] = fmaf(f0.y, w0, acc[1]);
        acc[2] = fmaf(f0.z, w1, acc[2]);  acc[3] = fmaf(f0.w, w1, acc[3]);
        acc[4] = fmaf(f1.x, w2, acc[4]);  acc[5] = fmaf(f1.y, w2, acc[5]);
        acc[6] = fmaf(f1.z, w3, acc[6]);  acc[7] = fmaf(f1.w, w3, acc[7]);
    }
    #pragma unroll
    for (int off = 16; off > 0; off >>= 1) {
        #pragma unroll
        for (int o = 0; o < 8; o++) acc[o] += __shfl_xor_sync(0xffffffffu, acc[o], off);
        #pragma unroll
        for (int h = 0; h < 4; h++) den[h] += __shfl_xor_sync(0xffffffffu, den[h], off);
    }
    if (lane == 0) {
        bool has = end > beg;
        float o0 = 0.f, o1 = 0.f;
        #pragma unroll
        for (int h = 0; h < 4; h++) {
            float r0 = has ? acc[2 * h] / den[h] : 0.f;
            float r1 = has ? acc[2 * h + 1] / den[h] : 0.f;
            r0 += r4[n * 8 + 2 * h] + b4[2 * h];
            r1 += r4[n * 8 + 2 * h + 1] + b4[2 * h + 1];
            float m = fmaxf(r0, r1);
            float e0 = expf(r0 - m), e1 = expf(r1 - m);
            float s = e0 + e1;
            o0 += e0 / s;
            o1 += e1 / s;
        }
        out[n * 2 + 0] = o0 * 0.25f;
        out[n * 2 + 1] = o1 * 0.25f;
    }
}

// ---------------- host launcher ----------------------------------------------
extern "C" void kernel_launch(void* const* d_in, const int* in_sizes, int n_in,
                              void* d_out, int out_size) {
    const float* x     = (const float*)d_in[0];
    const int*   src   = (const int*)  d_in[1];
    const int*   dst   = (const int*)  d_in[2];
    const float* W1    = (const float*)d_in[3];
    const float* al1   = (const float*)d_in[4];
    const float* ar1   = (const float*)d_in[5];
    const float* b1    = (const float*)d_in[6];
    const float* W2    = (const float*)d_in[7];
    const float* al2   = (const float*)d_in[8];
    const float* ar2   = (const float*)d_in[9];
    const float* b2    = (const float*)d_in[10];
    const float* W3    = (const float*)d_in[11];
    const float* al3   = (const float*)d_in[12];
    const float* ar3   = (const float*)d_in[13];
    const float* b3    = (const float*)d_in[14];
    const float* W4    = (const float*)d_in[15];
    const float* al4   = (const float*)d_in[16];
    const float* ar4   = (const float*)d_in[17];
    const float* b4    = (const float*)d_in[18];
    const float* resW4 = (const float*)d_in[19];
    float* out = (float*)d_out;
    const int E = in_sizes[1];

    __half *feath, *xh, *hAh, *hBh, *W1h, *W2h, *W3h;
    float *el, *er, *f4, *r4;
    int *cnt, *rowptr, *cur, *csrc;
    cudaGetSymbolAddress((void**)&feath,  g_feath);
    cudaGetSymbolAddress((void**)&xh,     g_xh);
    cudaGetSymbolAddress((void**)&hAh,    g_hAh);
    cudaGetSymbolAddress((void**)&hBh,    g_hBh);
    cudaGetSymbolAddress((void**)&W1h,    g_W1h);
    cudaGetSymbolAddress((void**)&W2h,    g_W2h);
    cudaGetSymbolAddress((void**)&W3h,    g_W3h);
    cudaGetSymbolAddress((void**)&el,     g_el);
    cudaGetSymbolAddress((void**)&er,     g_er);
    cudaGetSymbolAddress((void**)&f4,     g_f4);
    cudaGetSymbolAddress((void**)&r4,     g_r4);
    cudaGetSymbolAddress((void**)&cnt,    g_cnt);
    cudaGetSymbolAddress((void**)&rowptr, g_rowptr);
    cudaGetSymbolAddress((void**)&cur,    g_cur);
    cudaGetSymbolAddress((void**)&csrc,   g_csrc);

    cudaFuncSetAttribute(k_gemm_fp16,
                         cudaFuncAttributeMaxDynamicSharedMemorySize, GEMM_SMEM);

    const bool dual = (g_s2 != nullptr) && (g_evFork != nullptr) && (g_evJoin != nullptr);
    cudaStream_t sC = dual ? g_s2 : (cudaStream_t)0;   // CSR stream

    if (dual) {
        cudaEventRecord(g_evFork, 0);
        cudaStreamWaitEvent(g_s2, g_evFork, 0);
    }

    // ---- CSR by dst (side stream) ----
    k_zero_cnt<<<(NN + 255) / 256, 256, 0, sC>>>(cnt);
    k_histo<<<1024, 256, 0, sC>>>(dst, cnt, E);
    k_scan_part_fused<<<NB, 1024, 0, sC>>>(cnt, rowptr);
    k_scan_final<<<NB, 1024, 0, sC>>>(cnt, rowptr, cur);
    k_scatter<<<1024, 256, 0, sC>>>(src, dst, cur, csrc, E);
    if (dual) cudaEventRecord(g_evJoin, g_s2);

    // ---- converts + layer-1 GEMM (main stream, overlap with CSR) ----
    const int xn4 = NN * 128 / 4;
    k_cvtAll<<<(xn4 + 255) / 256, 256>>>((const float4*)x, (uint2*)xh, xn4,
                                         (const float4*)W1, (uint2*)W1h,
                                         (const float4*)W2, (uint2*)W2h,
                                         (const float4*)W3, (uint2*)W3h);

    dim3 gemm_grid(FD / BN, (NN + BM - 1) / BM);   // (2, 391)
    const int agg_grid = (NN + 3) / 4;

    k_gemm_fp16<<<gemm_grid, 256, GEMM_SMEM>>>(xh, W1h, feath, al1, ar1, el, er, NN, 128);

    if (dual) cudaStreamWaitEvent(0, g_evJoin, 0);   // join CSR before edge agg

    // ---- layer 1 ----
    k_edge_agg<<<agg_grid, 128>>>((const uint4*)feath, (const float4*)el,
                                  (const float4*)er, rowptr, csrc, nullptr,
                                  (const float4*)b1, (uint4*)hAh);

    // ---- layer 2 ----
    k_gemm_fp16<<<gemm_grid, 256, GEMM_SMEM>>>(hAh, W2h, feath, al2, ar2, el, er, NN, FD);
    k_edge_agg<<<agg_grid, 128>>>((const uint4*)feath, (const float4*)el,
                                  (const float4*)er, rowptr, csrc,
                                  (const uint4*)hAh, (const float4*)b2, (uint4*)hBh);

    // ---- layer 3 ----
    k_gemm_fp16<<<gemm_grid, 256, GEMM_SMEM>>>(hBh, W3h, feath, al3, ar3, el, er, NN, FD);
    k_edge_agg<<<agg_grid, 128>>>((const uint4*)feath, (const float4*)el,
                                  (const float4*)er, rowptr, csrc,
                                  (const uint4*)hBh, (const float4*)b3, (uint4*)hAh);

    // ---- layer 4 ----
    k_l4_proj<<<(NN + 7) / 8, 256>>>(hAh, W4, resW4, al4, ar4, f4, r4, el, er);
    k_l4_edge<<<(NN + 7) / 8, 256>>>(f4, el, er, rowptr, csrc, r4, b4, out);
}

// round 12
// speedup vs baseline: 1.1034x; 1.1034x over previous
#include <cuda_runtime.h>
#include <cuda_fp16.h>
#include <cstdint>
#include <cstring>

#define NN 50000
#define EE 800000
#define FD 256          // H*HID
#define NEG 0.2f
#define NB 49           // ceil(NN/1024)

__device__ __forceinline__ uint32_t h2_as_u32(__half2 v) {
    uint32_t u;
    memcpy(&u, &v, 4);
    return u;
}

// ---------------- scratch (device globals; no allocation allowed) ------------
__device__ __half g_feath[(size_t)NN * FD];   // fp16 post-GEMM features
__device__ __half g_xh[(size_t)NN * 128];     // fp16 input x
__device__ __half g_hAh[(size_t)NN * FD];     // fp16 h ping
__device__ __half g_hBh[(size_t)NN * FD];     // fp16 h pong
__device__ __half g_W1h[256 * 128];
__device__ __half g_W2h[256 * 256];
__device__ __half g_W3h[256 * 256];
__device__ float g_el[NN * 4];
__device__ float g_er[NN * 4];
__device__ float g_f4[NN * 8];
__device__ float g_r4[NN * 8];
__device__ int   g_cnt[NN];
__device__ int   g_rowptr[NN + 1];
__device__ int   g_cur[NN];
__device__ int   g_csrc[EE];
__device__ int   g_bsum[64];
__device__ int   g_tick;

// ---------------- merged fp32 -> fp16 converts (x + W1..W3) ------------------
__global__ void k_cvtAll(const float4* __restrict__ x, uint2* __restrict__ xo, int xn4,
                         const float4* __restrict__ w1, uint2* __restrict__ o1,
                         const float4* __restrict__ w2, uint2* __restrict__ o2,
                         const float4* __restrict__ w3, uint2* __restrict__ o3) {
    int i = blockIdx.x * blockDim.x + threadIdx.x;
    if (i < xn4) {
        float4 v = x[i];
        xo[i] = make_uint2(h2_as_u32(__floats2half2_rn(v.x, v.y)),
                           h2_as_u32(__floats2half2_rn(v.z, v.w)));
    }
    if (i < 8192) {
        float4 v = w1[i];
        o1[i] = make_uint2(h2_as_u32(__floats2half2_rn(v.x, v.y)),
                           h2_as_u32(__floats2half2_rn(v.z, v.w)));
    }
    if (i < 16384) {
        float4 v = w2[i];
        o2[i] = make_uint2(h2_as_u32(__floats2half2_rn(v.x, v.y)),
                           h2_as_u32(__floats2half2_rn(v.z, v.w)));
        float4 u = w3[i];
        o3[i] = make_uint2(h2_as_u32(__floats2half2_rn(u.x, u.y)),
                           h2_as_u32(__floats2half2_rn(u.z, u.w)));
    }
}

// ---------------- CSR build --------------------------------------------------
__global__ void k_zero_cnt(int* cnt) {
    int i = blockIdx.x * blockDim.x + threadIdx.x;
    if (i < NN) cnt[i] = 0;
}

__global__ void k_histo(const int* __restrict__ dst, int* __restrict__ cnt, int E) {
    for (int i = blockIdx.x * blockDim.x + threadIdx.x; i < E; i += gridDim.x * blockDim.x)
        atomicAdd(&cnt[dst[i]], 1);
}

// block sums + (last block) tiny scan of block sums, fused via ticket
__global__ void k_scan_part_fused(const int* __restrict__ cnt, int* __restrict__ rowptr) {
    __shared__ int sh[1024];
    __shared__ bool isLast;
    int tid = threadIdx.x;
    int i = blockIdx.x * 1024 + tid;
    sh[tid] = (i < NN) ? cnt[i] : 0;
    __syncthreads();
    for (int o = 512; o > 0; o >>= 1) {
        if (tid < o) sh[tid] += sh[tid + o];
        __syncthreads();
    }
    if (tid == 0) {
        g_bsum[blockIdx.x] = sh[0];
        __threadfence();
        int t = atomicAdd(&g_tick, 1);
        isLast = (t == gridDim.x - 1);
    }
    __syncthreads();
    if (isLast) {
        int v = 0;
        if (tid < 64) {
            v = (tid < NB) ? *((volatile int*)&g_bsum[tid]) : 0;
            sh[tid] = v;
        }
        __syncthreads();
        #pragma unroll
        for (int o = 1; o < 64; o <<= 1) {
            int u = (tid >= o && tid < 64) ? sh[tid - o] : 0;
            __syncthreads();
            if (tid < 64) sh[tid] += u;
            __syncthreads();
        }
        if (tid < NB) g_bsum[tid] = sh[tid] - v;   // exclusive prefix
        if (tid == 63) rowptr[NN] = sh[63];
        if (tid == 0) g_tick = 0;                  // reset for next call
    }
}

__global__ void k_scan_final(const int* __restrict__ cnt, int* __restrict__ rowptr,
                             int* __restrict__ cur) {
    __shared__ int sh[1024];
    int tid = threadIdx.x;
    int i = blockIdx.x * 1024 + tid;
    int v = (i < NN) ? cnt[i] : 0;
    sh[tid] = v;
    __syncthreads();
    #pragma unroll
    for (int o = 1; o < 1024; o <<= 1) {
        int t = (tid >= o) ? sh[tid - o] : 0;
        __syncthreads();
        sh[tid] += t;
        __syncthreads();
    }
    if (i < NN) { int ex = g_bsum[blockIdx.x] + sh[tid] - v; rowptr[i] = ex; cur[i] = ex; }
}

__global__ void k_scatter(const int* __restrict__ src, const int* __restrict__ dst,
                          int* __restrict__ cur, int* __restrict__ csrc, int E) {
    for (int i = blockIdx.x * blockDim.x + threadIdx.x; i < E; i += gridDim.x * blockDim.x) {
        int d = dst[i];
        int p = atomicAdd(&cur[d], 1);
        csrc[p] = src[i];
    }
}

// ---------------- fp16 GEMM BN=128 (cp.async dbuf) + fused el/er -------------
#define BM 128
#define BN 128
#define BKB 64                    // fp16 k per stage
#define BKBP 72                   // +8 pad
#define ASZB (BM * BKBP)
#define BSZB (BN * BKBP)
#define GEMM_SMEM ((2 * (ASZB + BSZB)) * (int)sizeof(__half))   // 73728 B

__device__ __forceinline__ void cp16(uint32_t s, const void* g) {
    asm volatile("cp.async.cg.shared.global [%0], [%1], 16;" :: "r"(s), "l"(g));
}

__device__ __forceinline__ void mma_fp16(float (&d)[4], const uint32_t (&a)[4],
                                         const uint32_t (&b)[2]) {
    asm volatile(
        "mma.sync.aligned.m16n8k16.row.col.f32.f16.f16.f32 "
        "{%0,%1,%2,%3},{%4,%5,%6,%7},{%8,%9},{%0,%1,%2,%3};"
        : "+f"(d[0]), "+f"(d[1]), "+f"(d[2]), "+f"(d[3])
        : "r"(a[0]), "r"(a[1]), "r"(a[2]), "r"(a[3]), "r"(b[0]), "r"(b[1]));
}

__global__ void __launch_bounds__(256) k_gemm_fp16(
        const __half* __restrict__ A, const __half* __restrict__ B,
        __half* __restrict__ C,
        const float* __restrict__ al, const float* __restrict__ ar,
        float* __restrict__ el, float* __restrict__ er, int M, int K) {
    extern __shared__ __half smem[];
    __half* Asm = smem;                 // [2][BM][BKBP]
    __half* Bsm = smem + 2 * ASZB;      // [2][BN][BKBP]
    __shared__ float sAl[BN], sAr[BN];

    const int bx = blockIdx.x;
    const int bm = blockIdx.y * BM, bn = bx * BN;
    const int tid = threadIdx.x;
    const int warp = tid >> 5, lane = tid & 31;
    const int wm = warp & 3, wn = warp >> 2;      // wn in {0,1}: head within block
    const int r = lane >> 2, c = lane & 3;
    const int hg = bx * 2 + wn;

    if (tid < BN) { sAl[tid] = al[bn + tid]; sAr[tid] = ar[bn + tid]; }

    const int lrow = tid >> 1, lcol = (tid & 1) * 32;
    const bool aok = (bm + lrow) < M;

    float acc[2][8][4];
    #pragma unroll
    for (int mt = 0; mt < 2; mt++)
        #pragma unroll
        for (int nt = 0; nt < 8; nt++)
            #pragma unroll
            for (int i = 0; i < 4; i++) acc[mt][nt][i] = 0.f;

    const int ntile = K / BKB;

    auto issue = [&](int buf, int kt) {
        if (aok) {
            uint32_t sa = (uint32_t)__cvta_generic_to_shared(
                &Asm[(buf * BM + lrow) * BKBP + lcol]);
            const __half* ga = &A[(size_t)(bm + lrow) * K + kt + lcol];
            #pragma unroll
            for (int j = 0; j < 4; j++) cp16(sa + j * 16, ga + j * 8);
        }
        uint32_t sb = (uint32_t)__cvta_generic_to_shared(
            &Bsm[(buf * BN + lrow) * BKBP + lcol]);
        const __half* gb = &B[(size_t)(bn + lrow) * K + kt + lcol];
        #pragma unroll
        for (int j = 0; j < 4; j++) cp16(sb + j * 16, gb + j * 8);
    };

    issue(0, 0);
    asm volatile("cp.async.commit_group;");

    for (int t = 0; t < ntile; t++) {
        if (t + 1 < ntile) {
            issue((t + 1) & 1, (t + 1) * BKB);
            asm volatile("cp.async.commit_group;");
            asm volatile("cp.async.wait_group 1;");
        } else {
            asm volatile("cp.async.wait_group 0;");
        }
        __syncthreads();
        const __half* Ab = &Asm[((t & 1) * BM) * BKBP];
        const __half* Bb = &Bsm[((t & 1) * BN) * BKBP];
        #pragma unroll
        for (int kk = 0; kk < BKB; kk += 16) {
            uint32_t af[2][4], bf[8][2];
            #pragma unroll
            for (int mt = 0; mt < 2; mt++) {
                int row0 = wm * 32 + mt * 16 + r;
                af[mt][0] = *(const uint32_t*)&Ab[row0 * BKBP + kk + 2 * c];
                af[mt][1] = *(const uint32_t*)&Ab[(row0 + 8) * BKBP + kk + 2 * c];
                af[mt][2] = *(const uint32_t*)&Ab[row0 * BKBP + kk + 2 * c + 8];
                af[mt][3] = *(const uint32_t*)&Ab[(row0 + 8) * BKBP + kk + 2 * c + 8];
            }
            #pragma unroll
            for (int nt = 0; nt < 8; nt++) {
                int col0 = wn * 64 + nt * 8 + r;
                bf[nt][0] = *(const uint32_t*)&Bb[col0 * BKBP + kk + 2 * c];
                bf[nt][1] = *(const uint32_t*)&Bb[col0 * BKBP + kk + 2 * c + 8];
            }
            #pragma unroll
            for (int mt = 0; mt < 2; mt++)
                #pragma unroll
                for (int nt = 0; nt < 8; nt++)
                    mma_fp16(acc[mt][nt], af[mt], bf[nt]);
        }
        __syncthreads();
    }

    // ---- store fp16 feat ----
    #pragma unroll
    for (int mt = 0; mt < 2; mt++) {
        #pragma unroll
        for (int nt = 0; nt < 8; nt++) {
            int row = bm + wm * 32 + mt * 16 + r;
            int col = bn + wn * 64 + nt * 8 + 2 * c;
            if (row < M)
                *(__half2*)&C[(size_t)row * FD + col] =
                    __floats2half2_rn(acc[mt][nt][0], acc[mt][nt][1]);
            if (row + 8 < M)
                *(__half2*)&C[(size_t)(row + 8) * FD + col] =
                    __floats2half2_rn(acc[mt][nt][2], acc[mt][nt][3]);
        }
    }

    // ---- fused el/er: warp owns (rows wm*32..+31, head hg); direct write ----
    #pragma unroll
    for (int mt = 0; mt < 2; mt++) {
        #pragma unroll
        for (int rh = 0; rh < 2; rh++) {
            float se = 0.f, sr2 = 0.f;
            #pragma unroll
            for (int nt = 0; nt < 8; nt++) {
                int col = wn * 64 + nt * 8 + 2 * c;
                float a0 = acc[mt][nt][rh * 2], a1 = acc[mt][nt][rh * 2 + 1];
                se  += a0 * sAl[col] + a1 * sAl[col + 1];
                sr2 += a0 * sAr[col] + a1 * sAr[col + 1];
            }
            se  += __shfl_xor_sync(0xffffffffu, se, 1);
            se  += __shfl_xor_sync(0xffffffffu, se, 2);
            sr2 += __shfl_xor_sync(0xffffffffu, sr2, 1);
            sr2 += __shfl_xor_sync(0xffffffffu, sr2, 2);
            if (c == 0) {
                int row = bm + wm * 32 + mt * 16 + rh * 8 + r;
                if (row < M) {
                    el[row * 4 + hg] = se;
                    er[row * 4 + hg] = sr2;
                }
            }
        }
    }
}

// ---------------- fused edge aggregation: warp per node, fp16 everywhere -----
__global__ void __launch_bounds__(128) k_edge_agg(
        const uint4* __restrict__ feath,      // [N][32] x (8 fp16)
        const float4* __restrict__ el4, const float4* __restrict__ er4,
        const int* __restrict__ rowptr, const int* __restrict__ csrc,
        const uint4* __restrict__ hprevh,     // fp16 prev h or null
        const float4* __restrict__ bias4,
        uint4* __restrict__ houth) {          // fp16 out h
    int w = threadIdx.x >> 5;
    int n = blockIdx.x * 4 + w;
    int lane = threadIdx.x & 31;
    if (n >= NN) return;
    int head = lane >> 3;
    __shared__ int   ssrc[4][32];
    __shared__ float sw[4][32][4];
    int beg = rowptr[n], end = rowptr[n + 1];
    float4 erd = er4[n];
    float acc[8];
    #pragma unroll
    for (int i = 0; i < 8; i++) acc[i] = 0.f;
    float4 dl = make_float4(0.f, 0.f, 0.f, 0.f);

    #define ACCUM(fv, wgt) do {                                             \
        const __half2* _p = (const __half2*)&(fv);                          \
        _Pragma("unroll")                                                   \
        for (int _j = 0; _j < 4; _j++) {                                    \
            float2 _v = __half22float2(_p[_j]);                             \
            acc[2 * _j]     = fmaf(_v.x, (wgt), acc[2 * _j]);               \
            acc[2 * _j + 1] = fmaf(_v.y, (wgt), acc[2 * _j + 1]);           \
        } } while (0)

    for (int base = beg; base < end; base += 32) {
        int cnt = min(32, end - base);
        if (lane < cnt) {
            int s = csrc[base + lane];
            ssrc[w][lane] = s;
            float4 le = el4[s];
            float x0 = le.x + erd.x; x0 = x0 > 0.f ? x0 : NEG * x0;
            float x1 = le.y + erd.y; x1 = x1 > 0.f ? x1 : NEG * x1;
            float x2 = le.z + erd.z; x2 = x2 > 0.f ? x2 : NEG * x2;
            float x3 = le.w + erd.w; x3 = x3 > 0.f ? x3 : NEG * x3;
            float w0 = expf(x0), w1 = expf(x1), w2 = expf(x2), w3 = expf(x3);
            sw[w][lane][0] = w0; sw[w][lane][1] = w1;
            sw[w][lane][2] = w2; sw[w][lane][3] = w3;
            dl.x += w0; dl.y += w1; dl.z += w2; dl.w += w3;
        }
        __syncwarp();
        int e = 0;
        for (; e + 4 <= cnt; e += 4) {
            uint4 f0 = feath[(size_t)ssrc[w][e]     * 32 + lane];
            uint4 f1 = feath[(size_t)ssrc[w][e + 1] * 32 + lane];
            uint4 f2 = feath[(size_t)ssrc[w][e + 2] * 32 + lane];
            uint4 f3 = feath[(size_t)ssrc[w][e + 3] * 32 + lane];
            float w0 = sw[w][e][head],     w1 = sw[w][e + 1][head];
            float w2 = sw[w][e + 2][head], w3 = sw[w][e + 3][head];
            ACCUM(f0, w0); ACCUM(f1, w1); ACCUM(f2, w2); ACCUM(f3, w3);
        }
        for (; e < cnt; e++) {
            uint4 fv = feath[(size_t)ssrc[w][e] * 32 + lane];
            float wg = sw[w][e][head];
            ACCUM(fv, wg);
        }
        __syncwarp();
    }
    #undef ACCUM

    #pragma unroll
    for (int o = 16; o > 0; o >>= 1) {
        dl.x += __shfl_xor_sync(0xffffffffu, dl.x, o);
        dl.y += __shfl_xor_sync(0xffffffffu, dl.y, o);
        dl.z += __shfl_xor_sync(0xffffffffu, dl.z, o);
        dl.w += __shfl_xor_sync(0xffffffffu, dl.w, o);
    }
    float den = (head == 0) ? dl.x : (head == 1) ? dl.y : (head == 2) ? dl.z : dl.w;
    float inv = (end > beg) ? 1.f / den : 0.f;
    float4 b0 = bias4[lane * 2], b1 = bias4[lane * 2 + 1];
    float v[8];
    v[0] = acc[0] * inv + b0.x; v[1] = acc[1] * inv + b0.y;
    v[2] = acc[2] * inv + b0.z; v[3] = acc[3] * inv + b0.w;
    v[4] = acc[4] * inv + b1.x; v[5] = acc[5] * inv + b1.y;
    v[6] = acc[6] * inv + b1.z; v[7] = acc[7] * inv + b1.w;
    if (hprevh) {
        uint4 pv = hprevh[(size_t)n * 32 + lane];
        const __half2* pp = (const __half2*)&pv;
        #pragma unroll
        for (int j = 0; j < 4; j++) {
            float2 p = __half22float2(pp[j]);
            v[2 * j]     += p.x;
            v[2 * j + 1] += p.y;
        }
    }
    #pragma unroll
    for (int j = 0; j < 8; j++)
        v[j] = v[j] > 0.f ? v[j] : expm1f(v[j]);
    uint4 ob;
    ob.x = h2_as_u32(__floats2half2_rn(v[0], v[1]));
    ob.y = h2_as_u32(__floats2half2_rn(v[2], v[3]));
    ob.z = h2_as_u32(__floats2half2_rn(v[4], v[5]));
    ob.w = h2_as_u32(__floats2half2_rn(v[6], v[7]));
    houth[(size_t)n * 32 + lane] = ob;
}

// ---------------- layer-4 projection + el/er (merged, fp16 h) ----------------
__global__ void k_l4_proj(const __half* __restrict__ h, const float* __restrict__ W4,
                          const float* __restrict__ rW4,
                          const float* __restrict__ al4, const float* __restrict__ ar4,
                          float* __restrict__ f4, float* __restrict__ r4,
                          float* __restrict__ el, float* __restrict__ er) {
    int n = blockIdx.x * 8 + (threadIdx.x >> 5);
    int lane = threadIdx.x & 31;
    if (n >= NN) return;
    float acc[16];
    #pragma unroll
    for (int o = 0; o < 16; o++) acc[o] = 0.f;
    const __half* hr = h + (size_t)n * FD;
    #pragma unroll
    for (int k8 = 0; k8 < 8; k8++) {
        int k = k8 * 32 + lane;
        float hv = __half2float(hr[k]);
        #pragma unroll
        for (int o = 0; o < 8; o++) acc[o]     = fmaf(hv, W4[o * FD + k], acc[o]);
        #pragma unroll
        for (int o = 0; o < 8; o++) acc[8 + o] = fmaf(hv, rW4[o * FD + k], acc[8 + o]);
    }
    #pragma unroll
    for (int o = 0; o < 16; o++)
        #pragma unroll
        for (int off = 16; off > 0; off >>= 1)
            acc[o] += __shfl_xor_sync(0xffffffffu, acc[o], off);
    if (lane < 8) {
        f4[n * 8 + lane] = acc[lane];
        r4[n * 8 + lane] = acc[8 + lane];
    }
    if (lane < 4) {
        el[n * 4 + lane] = acc[2 * lane] * al4[2 * lane] +
                           acc[2 * lane + 1] * al4[2 * lane + 1];
        er[n * 4 + lane] = acc[2 * lane] * ar4[2 * lane] +
                           acc[2 * lane + 1] * ar4[2 * lane + 1];
    }
}

// ---------------- layer-4 edge agg + softmax + head-mean ---------------------
__global__ void k_l4_edge(const float* __restrict__ f4, const float* __restrict__ el,
                          const float* __restrict__ er, const int* __restrict__ rowptr,
                          const int* __restrict__ csrc, const float* __restrict__ r4,
                          const float* __restrict__ b4, float* __restrict__ out) {
    int n = blockIdx.x * 8 + (threadIdx.x >> 5);
    int lane = threadIdx.x & 31;
    if (n >= NN) return;
    int beg = rowptr[n], end = rowptr[n + 1];
    float4 erd = ((const float4*)er)[n];
    float acc[8] = {0, 0, 0, 0, 0, 0, 0, 0};
    float den[4] = {0, 0, 0, 0};
    for (int e = beg + lane; e < end; e += 32) {
        int s = csrc[e];
        float4 le = ((const float4*)el)[s];
        float x0 = le.x + erd.x; x0 = x0 > 0.f ? x0 : NEG * x0;
        float x1 = le.y + erd.y; x1 = x1 > 0.f ? x1 : NEG * x1;
        float x2 = le.z + erd.z; x2 = x2 > 0.f ? x2 : NEG * x2;
        float x3 = le.w + erd.w; x3 = x3 > 0.f ? x3 : NEG * x3;
        float w0 = expf(x0), w1 = expf(x1), w2 = expf(x2), w3 = expf(x3);
        den[0] += w0; den[1] += w1; den[2] += w2; den[3] += w3;
        float4 f0 = ((const float4*)f4)[s * 2];
        float4 f1 = ((const float4*)f4)[s * 2 + 1];
        acc[0] = fmaf(f0.x, w0, acc[0]);  acc[1] = fmaf(f0.y, w0, acc[1]);
        acc[2] = fmaf(f0.z, w1, acc[2]);  acc[3] = fmaf(f0.w, w1, acc[3]);
        acc[4] = fmaf(f1.x, w2, acc[4]);  acc[5] = fmaf(f1.y, w2, acc[5]);
        acc[6] = fmaf(f1.z, w3, acc[6]);  acc[7] = fmaf(f1.w, w3, acc[7]);
    }
    #pragma unroll
    for (int off = 16; off > 0; off >>= 1) {
        #pragma unroll
        for (int o = 0; o < 8; o++) acc[o] += __shfl_xor_sync(0xffffffffu, acc[o], off);
        #pragma unroll
        for (int h = 0; h < 4; h++) den[h] += __shfl_xor_sync(0xffffffffu, den[h], off);
    }
    if (lane == 0) {
        bool has = end > beg;
        float o0 = 0.f, o1 = 0.f;
        #pragma unroll
        for (int h = 0; h < 4; h++) {
            float r0 = has ? acc[2 * h] / den[h] : 0.f;
            float r1 = has ? acc[2 * h + 1] / den[h] : 0.f;
            r0 += r4[n * 8 + 2 * h] + b4[2 * h];
            r1 += r4[n * 8 + 2 * h + 1] + b4[2 * h + 1];
            float m = fmaxf(r0, r1);
            float e0 = expf(r0 - m), e1 = expf(r1 - m);
            float s = e0 + e1;
            o0 += e0 / s;
            o1 += e1 / s;
        }
        out[n * 2 + 0] = o0 * 0.25f;
        out[n * 2 + 1] = o1 * 0.25f;
    }
}

// ---------------- host launcher ----------------------------------------------
extern "C" void kernel_launch(void* const* d_in, const int* in_sizes, int n_in,
                              void* d_out, int out_size) {
    const float* x     = (const float*)d_in[0];
    const int*   src   = (const int*)  d_in[1];
    const int*   dst   = (const int*)  d_in[2];
    const float* W1    = (const float*)d_in[3];
    const float* al1   = (const float*)d_in[4];
    const float* ar1   = (const float*)d_in[5];
    const float* b1    = (const float*)d_in[6];
    const float* W2    = (const float*)d_in[7];
    const float* al2   = (const float*)d_in[8];
    const float* ar2   = (const float*)d_in[9];
    const float* b2    = (const float*)d_in[10];
    const float* W3    = (const float*)d_in[11];
    const float* al3   = (const float*)d_in[12];
    const float* ar3   = (const float*)d_in[13];
    const float* b3    = (const float*)d_in[14];
    const float* W4    = (const float*)d_in[15];
    const float* al4   = (const float*)d_in[16];
    const float* ar4   = (const float*)d_in[17];
    const float* b4    = (const float*)d_in[18];
    const float* resW4 = (const float*)d_in[19];
    float* out = (float*)d_out;
    const int E = in_sizes[1];

    __half *feath, *xh, *hAh, *hBh, *W1h, *W2h, *W3h;
    float *el, *er, *f4, *r4;
    int *cnt, *rowptr, *cur, *csrc;
    cudaGetSymbolAddress((void**)&feath,  g_feath);
    cudaGetSymbolAddress((void**)&xh,     g_xh);
    cudaGetSymbolAddress((void**)&hAh,    g_hAh);
    cudaGetSymbolAddress((void**)&hBh,    g_hBh);
    cudaGetSymbolAddress((void**)&W1h,    g_W1h);
    cudaGetSymbolAddress((void**)&W2h,    g_W2h);
    cudaGetSymbolAddress((void**)&W3h,    g_W3h);
    cudaGetSymbolAddress((void**)&el,     g_el);
    cudaGetSymbolAddress((void**)&er,     g_er);
    cudaGetSymbolAddress((void**)&f4,     g_f4);
    cudaGetSymbolAddress((void**)&r4,     g_r4);
    cudaGetSymbolAddress((void**)&cnt,    g_cnt);
    cudaGetSymbolAddress((void**)&rowptr, g_rowptr);
    cudaGetSymbolAddress((void**)&cur,    g_cur);
    cudaGetSymbolAddress((void**)&csrc,   g_csrc);

    cudaFuncSetAttribute(k_gemm_fp16,
                         cudaFuncAttributeMaxDynamicSharedMemorySize, GEMM_SMEM);

    // ---- converts (single stream) ----
    const int xn4 = NN * 128 / 4;
    k_cvtAll<<<(xn4 + 255) / 256, 256>>>((const float4*)x, (uint2*)xh, xn4,
                                         (const float4*)W1, (uint2*)W1h,
                                         (const float4*)W2, (uint2*)W2h,
                                         (const float4*)W3, (uint2*)W3h);

    // ---- CSR by dst ----
    k_zero_cnt<<<(NN + 255) / 256, 256>>>(cnt);
    k_histo<<<1024, 256>>>(dst, cnt, E);
    k_scan_part_fused<<<NB, 1024>>>(cnt, rowptr);
    k_scan_final<<<NB, 1024>>>(cnt, rowptr, cur);
    k_scatter<<<1024, 256>>>(src, dst, cur, csrc, E);

    dim3 gemm_grid(FD / BN, (NN + BM - 1) / BM);   // (2, 391)
    const int agg_grid = (NN + 3) / 4;

    // ---- layer 1 ----
    k_gemm_fp16<<<gemm_grid, 256, GEMM_SMEM>>>(xh, W1h, feath, al1, ar1, el, er, NN, 128);
    k_edge_agg<<<agg_grid, 128>>>((const uint4*)feath, (const float4*)el,
                                  (const float4*)er, rowptr, csrc, nullptr,
                                  (const float4*)b1, (uint4*)hAh);

    // ---- layer 2 ----
    k_gemm_fp16<<<gemm_grid, 256, GEMM_SMEM>>>(hAh, W2h, feath, al2, ar2, el, er, NN, FD);
    k_edge_agg<<<agg_grid, 128>>>((const uint4*)feath, (const float4*)el,
                                  (const float4*)er, rowptr, csrc,
                                  (const uint4*)hAh, (const float4*)b2, (uint4*)hBh);

    // ---- layer 3 ----
    k_gemm_fp16<<<gemm_grid, 256, GEMM_SMEM>>>(hBh, W3h, feath, al3, ar3, el, er, NN, FD);
    k_edge_agg<<<agg_grid, 128>>>((const uint4*)feath, (const float4*)el,
                                  (const float4*)er, rowptr, csrc,
                                  (const uint4*)hBh, (const float4*)b3, (uint4*)hAh);

    // ---- layer 4 ----
    k_l4_proj<<<(NN + 7) / 8, 256>>>(hAh, W4, resW4, al4, ar4, f4, r4, el, er);
    k_l4_edge<<<(NN + 7) / 8, 256>>>(f4, el, er, rowptr, csrc, r4, b4, out);
}

// round 13
// speedup vs baseline: 1.6566x; 1.5015x over previous
#include <cuda_runtime.h>
#include <cuda_fp16.h>
#include <cstdint>
#include <cstring>

#define NN 50000
#define EE 800000
#define FD 256          // H*HID
#define NEG 0.2f
#define NB 49           // ceil(NN/1024)

__device__ __forceinline__ uint32_t h2_as_u32(__half2 v) {
    uint32_t u;
    memcpy(&u, &v, 4);
    return u;
}

// ---------------- scratch (device globals; no allocation allowed) ------------
__device__ __half g_feath[(size_t)NN * FD];   // fp16 post-GEMM features
__device__ __half g_xh[(size_t)NN * 128];     // fp16 input x
__device__ __half g_hAh[(size_t)NN * FD];     // fp16 h ping
__device__ __half g_hBh[(size_t)NN * FD];     // fp16 h pong
__device__ __half g_W1h[256 * 128];
__device__ __half g_W2h[256 * 256];
__device__ __half g_W3h[256 * 256];
__device__ float g_el[NN * 4];
__device__ float g_er[NN * 4];
__device__ float g_f4[NN * 8];
__device__ float g_r4[NN * 8];
__device__ int   g_cnt[NN];
__device__ int   g_rowptr[NN + 1];
__device__ int   g_cur[NN];
__device__ int   g_csrc[EE];
__device__ int   g_bsum[64];

// ---------------- merged fp32 -> fp16 converts (x + W1..W3) ------------------
__global__ void k_cvtAll(const float4* __restrict__ x, uint2* __restrict__ xo, int xn4,
                         const float4* __restrict__ w1, uint2* __restrict__ o1,
                         const float4* __restrict__ w2, uint2* __restrict__ o2,
                         const float4* __restrict__ w3, uint2* __restrict__ o3) {
    int i = blockIdx.x * blockDim.x + threadIdx.x;
    if (i < xn4) {
        float4 v = x[i];
        xo[i] = make_uint2(h2_as_u32(__floats2half2_rn(v.x, v.y)),
                           h2_as_u32(__floats2half2_rn(v.z, v.w)));
    }
    if (i < 8192) {
        float4 v = w1[i];
        o1[i] = make_uint2(h2_as_u32(__floats2half2_rn(v.x, v.y)),
                           h2_as_u32(__floats2half2_rn(v.z, v.w)));
    }
    if (i < 16384) {
        float4 v = w2[i];
        o2[i] = make_uint2(h2_as_u32(__floats2half2_rn(v.x, v.y)),
                           h2_as_u32(__floats2half2_rn(v.z, v.w)));
        float4 u = w3[i];
        o3[i] = make_uint2(h2_as_u32(__floats2half2_rn(u.x, u.y)),
                           h2_as_u32(__floats2half2_rn(u.z, u.w)));
    }
}

// ---------------- CSR build --------------------------------------------------
__global__ void k_zero_cnt(int* cnt) {
    int i = blockIdx.x * blockDim.x + threadIdx.x;
    if (i < NN) cnt[i] = 0;
}

__global__ void k_histo(const int* __restrict__ dst, int* __restrict__ cnt, int E) {
    for (int i = blockIdx.x * blockDim.x + threadIdx.x; i < E; i += gridDim.x * blockDim.x)
        atomicAdd(&cnt[dst[i]], 1);
}

__global__ void k_scan_part(const int* __restrict__ cnt) {
    __shared__ int sh[1024];
    int i = blockIdx.x * 1024 + threadIdx.x;
    sh[threadIdx.x] = (i < NN) ? cnt[i] : 0;
    __syncthreads();
    for (int o = 512; o > 0; o >>= 1) {
        if (threadIdx.x < o) sh[threadIdx.x] += sh[threadIdx.x + o];
        __syncthreads();
    }
    if (threadIdx.x == 0) g_bsum[blockIdx.x] = sh[0];
}

__global__ void k_scan_small(int* rowptr) {
    __shared__ int sh[64];
    int t = threadIdx.x;
    int v = (t < NB) ? g_bsum[t] : 0;
    sh[t] = v;
    __syncthreads();
    #pragma unroll
    for (int o = 1; o < 64; o <<= 1) {
        int u = (t >= o) ? sh[t - o] : 0;
        __syncthreads();
        sh[t] += u;
        __syncthreads();
    }
    if (t < NB) g_bsum[t] = sh[t] - v;       // exclusive prefix
    if (t == 63) rowptr[NN] = sh[63];
}

__global__ void k_scan_final(const int* __restrict__ cnt, int* __restrict__ rowptr,
                             int* __restrict__ cur) {
    __shared__ int sh[1024];
    int tid = threadIdx.x;
    int i = blockIdx.x * 1024 + tid;
    int v = (i < NN) ? cnt[i] : 0;
    sh[tid] = v;
    __syncthreads();
    #pragma unroll
    for (int o = 1; o < 1024; o <<= 1) {
        int t = (tid >= o) ? sh[tid - o] : 0;
        __syncthreads();
        sh[tid] += t;
        __syncthreads();
    }
    if (i < NN) { int ex = g_bsum[blockIdx.x] + sh[tid] - v; rowptr[i] = ex; cur[i] = ex; }
}

__global__ void k_scatter(const int* __restrict__ src, const int* __restrict__ dst,
                          int* __restrict__ cur, int* __restrict__ csrc, int E) {
    for (int i = blockIdx.x * blockDim.x + threadIdx.x; i < E; i += gridDim.x * blockDim.x) {
        int d = dst[i];
        int p = atomicAdd(&cur[d], 1);
        csrc[p] = src[i];
    }
}

// ---------------- fp16 GEMM BN=128 (cp.async dbuf) + fused el/er -------------
#define BM 128
#define BN 128
#define BKB 64                    // fp16 k per stage
#define BKBP 72                   // +8 pad
#define ASZB (BM * BKBP)
#define BSZB (BN * BKBP)
#define GEMM_SMEM ((2 * (ASZB + BSZB)) * (int)sizeof(__half))   // 73728 B

__device__ __forceinline__ void cp16(uint32_t s, const void* g) {
    asm volatile("cp.async.cg.shared.global [%0], [%1], 16;" :: "r"(s), "l"(g));
}

__device__ __forceinline__ void mma_fp16(float (&d)[4], const uint32_t (&a)[4],
                                         const uint32_t (&b)[2]) {
    asm volatile(
        "mma.sync.aligned.m16n8k16.row.col.f32.f16.f16.f32 "
        "{%0,%1,%2,%3},{%4,%5,%6,%7},{%8,%9},{%0,%1,%2,%3};"
        : "+f"(d[0]), "+f"(d[1]), "+f"(d[2]), "+f"(d[3])
        : "r"(a[0]), "r"(a[1]), "r"(a[2]), "r"(a[3]), "r"(b[0]), "r"(b[1]));
}

__global__ void __launch_bounds__(256) k_gemm_fp16(
        const __half* __restrict__ A, const __half* __restrict__ B,
        __half* __restrict__ C,
        const float* __restrict__ al, const float* __restrict__ ar,
        float* __restrict__ el, float* __restrict__ er, int M, int K) {
    extern __shared__ __half smem[];
    __half* Asm = smem;                 // [2][BM][BKBP]
    __half* Bsm = smem + 2 * ASZB;      // [2][BN][BKBP]
    __shared__ float sAl[BN], sAr[BN];

    const int bx = blockIdx.x;
    const int bm = blockIdx.y * BM, bn = bx * BN;
    const int tid = threadIdx.x;
    const int warp = tid >> 5, lane = tid & 31;
    const int wm = warp & 3, wn = warp >> 2;      // wn in {0,1}: head within block
    const int r = lane >> 2, c = lane & 3;
    const int hg = bx * 2 + wn;

    if (tid < BN) { sAl[tid] = al[bn + tid]; sAr[tid] = ar[bn + tid]; }

    const int lrow = tid >> 1, lcol = (tid & 1) * 32;
    const bool aok = (bm + lrow) < M;

    float acc[2][8][4];
    #pragma unroll
    for (int mt = 0; mt < 2; mt++)
        #pragma unroll
        for (int nt = 0; nt < 8; nt++)
            #pragma unroll
            for (int i = 0; i < 4; i++) acc[mt][nt][i] = 0.f;

    const int ntile = K / BKB;

    auto issue = [&](int buf, int kt) {
        if (aok) {
            uint32_t sa = (uint32_t)__cvta_generic_to_shared(
                &Asm[(buf * BM + lrow) * BKBP + lcol]);
            const __half* ga = &A[(size_t)(bm + lrow) * K + kt + lcol];
            #pragma unroll
            for (int j = 0; j < 4; j++) cp16(sa + j * 16, ga + j * 8);
        }
        uint32_t sb = (uint32_t)__cvta_generic_to_shared(
            &Bsm[(buf * BN + lrow) * BKBP + lcol]);
        const __half* gb = &B[(size_t)(bn + lrow) * K + kt + lcol];
        #pragma unroll
        for (int j = 0; j < 4; j++) cp16(sb + j * 16, gb + j * 8);
    };

    issue(0, 0);
    asm volatile("cp.async.commit_group;");

    for (int t = 0; t < ntile; t++) {
        if (t + 1 < ntile) {
            issue((t + 1) & 1, (t + 1) * BKB);
            asm volatile("cp.async.commit_group;");
            asm volatile("cp.async.wait_group 1;");
        } else {
            asm volatile("cp.async.wait_group 0;");
        }
        __syncthreads();
        const __half* Ab = &Asm[((t & 1) * BM) * BKBP];
        const __half* Bb = &Bsm[((t & 1) * BN) * BKBP];
        #pragma unroll
        for (int kk = 0; kk < BKB; kk += 16) {
            uint32_t af[2][4], bf[8][2];
            #pragma unroll
            for (int mt = 0; mt < 2; mt++) {
                int row0 = wm * 32 + mt * 16 + r;
                af[mt][0] = *(const uint32_t*)&Ab[row0 * BKBP + kk + 2 * c];
                af[mt][1] = *(const uint32_t*)&Ab[(row0 + 8) * BKBP + kk + 2 * c];
                af[mt][2] = *(const uint32_t*)&Ab[row0 * BKBP + kk + 2 * c + 8];
                af[mt][3] = *(const uint32_t*)&Ab[(row0 + 8) * BKBP + kk + 2 * c + 8];
            }
            #pragma unroll
            for (int nt = 0; nt < 8; nt++) {
                int col0 = wn * 64 + nt * 8 + r;
                bf[nt][0] = *(const uint32_t*)&Bb[col0 * BKBP + kk + 2 * c];
                bf[nt][1] = *(const uint32_t*)&Bb[col0 * BKBP + kk + 2 * c + 8];
            }
            #pragma unroll
            for (int mt = 0; mt < 2; mt++)
                #pragma unroll
                for (int nt = 0; nt < 8; nt++)
                    mma_fp16(acc[mt][nt], af[mt], bf[nt]);
        }
        __syncthreads();
    }

    // ---- store fp16 feat ----
    #pragma unroll
    for (int mt = 0; mt < 2; mt++) {
        #pragma unroll
        for (int nt = 0; nt < 8; nt++) {
            int row = bm + wm * 32 + mt * 16 + r;
            int col = bn + wn * 64 + nt * 8 + 2 * c;
            if (row < M)
                *(__half2*)&C[(size_t)row * FD + col] =
                    __floats2half2_rn(acc[mt][nt][0], acc[mt][nt][1]);
            if (row + 8 < M)
                *(__half2*)&C[(size_t)(row + 8) * FD + col] =
                    __floats2half2_rn(acc[mt][nt][2], acc[mt][nt][3]);
        }
    }

    // ---- fused el/er: warp owns (rows wm*32..+31, head hg); direct write ----
    #pragma unroll
    for (int mt = 0; mt < 2; mt++) {
        #pragma unroll
        for (int rh = 0; rh < 2; rh++) {
            float se = 0.f, sr2 = 0.f;
            #pragma unroll
            for (int nt = 0; nt < 8; nt++) {
                int col = wn * 64 + nt * 8 + 2 * c;
                float a0 = acc[mt][nt][rh * 2], a1 = acc[mt][nt][rh * 2 + 1];
                se  += a0 * sAl[col] + a1 * sAl[col + 1];
                sr2 += a0 * sAr[col] + a1 * sAr[col + 1];
            }
            se  += __shfl_xor_sync(0xffffffffu, se, 1);
            se  += __shfl_xor_sync(0xffffffffu, se, 2);
            sr2 += __shfl_xor_sync(0xffffffffu, sr2, 1);
            sr2 += __shfl_xor_sync(0xffffffffu, sr2, 2);
            if (c == 0) {
                int row = bm + wm * 32 + mt * 16 + rh * 8 + r;
                if (row < M) {
                    el[row * 4 + hg] = se;
                    er[row * 4 + hg] = sr2;
                }
            }
        }
    }
}

// ---------------- fused edge aggregation: warp per node, fp16 everywhere -----
__global__ void __launch_bounds__(128) k_edge_agg(
        const uint4* __restrict__ feath,      // [N][32] x (8 fp16)
        const float4* __restrict__ el4, const float4* __restrict__ er4,
        const int* __restrict__ rowptr, const int* __restrict__ csrc,
        const uint4* __restrict__ hprevh,     // fp16 prev h or null
        const float4* __restrict__ bias4,
        uint4* __restrict__ houth) {          // fp16 out h
    int w = threadIdx.x >> 5;
    int n = blockIdx.x * 4 + w;
    int lane = threadIdx.x & 31;
    if (n >= NN) return;
    int head = lane >> 3;
    __shared__ int   ssrc[4][32];
    __shared__ float sw[4][32][4];
    int beg = rowptr[n], end = rowptr[n + 1];
    float4 erd = er4[n];
    float acc[8];
    #pragma unroll
    for (int i = 0; i < 8; i++) acc[i] = 0.f;
    float4 dl = make_float4(0.f, 0.f, 0.f, 0.f);

    #define ACCUM(fv, wgt) do {                                             \
        const __half2* _p = (const __half2*)&(fv);                          \
        _Pragma("unroll")                                                   \
        for (int _j = 0; _j < 4; _j++) {                                    \
            float2 _v = __half22float2(_p[_j]);                             \
            acc[2 * _j]     = fmaf(_v.x, (wgt), acc[2 * _j]);               \
            acc[2 * _j + 1] = fmaf(_v.y, (wgt), acc[2 * _j + 1]);           \
        } } while (0)

    for (int base = beg; base < end; base += 32) {
        int cnt = min(32, end - base);
        if (lane < cnt) {
            int s = csrc[base + lane];
            ssrc[w][lane] = s;
            float4 le = el4[s];
            float x0 = le.x + erd.x; x0 = x0 > 0.f ? x0 : NEG * x0;
            float x1 = le.y + erd.y; x1 = x1 > 0.f ? x1 : NEG * x1;
            float x2 = le.z + erd.z; x2 = x2 > 0.f ? x2 : NEG * x2;
            float x3 = le.w + erd.w; x3 = x3 > 0.f ? x3 : NEG * x3;
            float w0 = expf(x0), w1 = expf(x1), w2 = expf(x2), w3 = expf(x3);
            sw[w][lane][0] = w0; sw[w][lane][1] = w1;
            sw[w][lane][2] = w2; sw[w][lane][3] = w3;
            dl.x += w0; dl.y += w1; dl.z += w2; dl.w += w3;
        }
        __syncwarp();
        int e = 0;
        for (; e + 4 <= cnt; e += 4) {
            uint4 f0 = feath[(size_t)ssrc[w][e]     * 32 + lane];
            uint4 f1 = feath[(size_t)ssrc[w][e + 1] * 32 + lane];
            uint4 f2 = feath[(size_t)ssrc[w][e + 2] * 32 + lane];
            uint4 f3 = feath[(size_t)ssrc[w][e + 3] * 32 + lane];
            float w0 = sw[w][e][head],     w1 = sw[w][e + 1][head];
            float w2 = sw[w][e + 2][head], w3 = sw[w][e + 3][head];
            ACCUM(f0, w0); ACCUM(f1, w1); ACCUM(f2, w2); ACCUM(f3, w3);
        }
        for (; e < cnt; e++) {
            uint4 fv = feath[(size_t)ssrc[w][e] * 32 + lane];
            float wg = sw[w][e][head];
            ACCUM(fv, wg);
        }
        __syncwarp();
    }
    #undef ACCUM

    #pragma unroll
    for (int o = 16; o > 0; o >>= 1) {
        dl.x += __shfl_xor_sync(0xffffffffu, dl.x, o);
        dl.y += __shfl_xor_sync(0xffffffffu, dl.y, o);
        dl.z += __shfl_xor_sync(0xffffffffu, dl.z, o);
        dl.w += __shfl_xor_sync(0xffffffffu, dl.w, o);
    }
    float den = (head == 0) ? dl.x : (head == 1) ? dl.y : (head == 2) ? dl.z : dl.w;
    float inv = (end > beg) ? 1.f / den : 0.f;
    float4 b0 = bias4[lane * 2], b1 = bias4[lane * 2 + 1];
    float v[8];
    v[0] = acc[0] * inv + b0.x; v[1] = acc[1] * inv + b0.y;
    v[2] = acc[2] * inv + b0.z; v[3] = acc[3] * inv + b0.w;
    v[4] = acc[4] * inv + b1.x; v[5] = acc[5] * inv + b1.y;
    v[6] = acc[6] * inv + b1.z; v[7] = acc[7] * inv + b1.w;
    if (hprevh) {
        uint4 pv = hprevh[(size_t)n * 32 + lane];
        const __half2* pp = (const __half2*)&pv;
        #pragma unroll
        for (int j = 0; j < 4; j++) {
            float2 p = __half22float2(pp[j]);
            v[2 * j]     += p.x;
            v[2 * j + 1] += p.y;
        }
    }
    #pragma unroll
    for (int j = 0; j < 8; j++)
        v[j] = v[j] > 0.f ? v[j] : expm1f(v[j]);
    uint4 ob;
    ob.x = h2_as_u32(__floats2half2_rn(v[0], v[1]));
    ob.y = h2_as_u32(__floats2half2_rn(v[2], v[3]));
    ob.z = h2_as_u32(__floats2half2_rn(v[4], v[5]));
    ob.w = h2_as_u32(__floats2half2_rn(v[6], v[7]));
    houth[(size_t)n * 32 + lane] = ob;
}

// ---------------- layer-4 projection + el/er (merged, fp16 h) ----------------
__global__ void k_l4_proj(const __half* __restrict__ h, const float* __restrict__ W4,
                          const float* __restrict__ rW4,
                          const float* __restrict__ al4, const float* __restrict__ ar4,
                          float* __restrict__ f4, float* __restrict__ r4,
                          float* __restrict__ el, float* __restrict__ er) {
    int n = blockIdx.x * 8 + (threadIdx.x >> 5);
    int lane = threadIdx.x & 31;
    if (n >= NN) return;
    float acc[16];
    #pragma unroll
    for (int o = 0; o < 16; o++) acc[o] = 0.f;
    const __half* hr = h + (size_t)n * FD;
    #pragma unroll
    for (int k8 = 0; k8 < 8; k8++) {
        int k = k8 * 32 + lane;
        float hv = __half2float(hr[k]);
        #pragma unroll
        for (int o = 0; o < 8; o++) acc[o]     = fmaf(hv, W4[o * FD + k], acc[o]);
        #pragma unroll
        for (int o = 0; o < 8; o++) acc[8 + o] = fmaf(hv, rW4[o * FD + k], acc[8 + o]);
    }
    #pragma unroll
    for (int o = 0; o < 16; o++)
        #pragma unroll
        for (int off = 16; off > 0; off >>= 1)
            acc[o] += __shfl_xor_sync(0xffffffffu, acc[o], off);
    if (lane < 8) {
        f4[n * 8 + lane] = acc[lane];
        r4[n * 8 + lane] = acc[8 + lane];
    }
    if (lane < 4) {
        el[n * 4 + lane] = acc[2 * lane] * al4[2 * lane] +
                           acc[2 * lane + 1] * al4[2 * lane + 1];
        er[n * 4 + lane] = acc[2 * lane] * ar4[2 * lane] +
                           acc[2 * lane + 1] * ar4[2 * lane + 1];
    }
}

// ---------------- layer-4 edge agg + softmax + head-mean ---------------------
__global__ void k_l4_edge(const float* __restrict__ f4, const float* __restrict__ el,
                          const float* __restrict__ er, const int* __restrict__ rowptr,
                          const int* __restrict__ csrc, const float* __restrict__ r4,
                          const float* __restrict__ b4, float* __restrict__ out) {
    int n = blockIdx.x * 8 + (threadIdx.x >> 5);
    int lane = threadIdx.x & 31;
    if (n >= NN) return;
    int beg = rowptr[n], end = rowptr[n + 1];
    float4 erd = ((const float4*)er)[n];
    float acc[8] = {0, 0, 0, 0, 0, 0, 0, 0};
    float den[4] = {0, 0, 0, 0};
    for (int e = beg + lane; e < end; e += 32) {
        int s = csrc[e];
        float4 le = ((const float4*)el)[s];
        float x0 = le.x + erd.x; x0 = x0 > 0.f ? x0 : NEG * x0;
        float x1 = le.y + erd.y; x1 = x1 > 0.f ? x1 : NEG * x1;
        float x2 = le.z + erd.z; x2 = x2 > 0.f ? x2 : NEG * x2;
        float x3 = le.w + erd.w; x3 = x3 > 0.f ? x3 : NEG * x3;
        float w0 = expf(x0), w1 = expf(x1), w2 = expf(x2), w3 = expf(x3);
        den[0] += w0; den[1] += w1; den[2] += w2; den[3] += w3;
        float4 f0 = ((const float4*)f4)[s * 2];
        float4 f1 = ((const float4*)f4)[s * 2 + 1];
        acc[0] = fmaf(f0.x, w0, acc[0]);  acc[1] = fmaf(f0.y, w0, acc[1]);
        acc[2] = fmaf(f0.z, w1, acc[2]);  acc[3] = fmaf(f0.w, w1, acc[3]);
        acc[4] = fmaf(f1.x, w2, acc[4]);  acc[5] = fmaf(f1.y, w2, acc[5]);
        acc[6] = fmaf(f1.z, w3, acc[6]);  acc[7] = fmaf(f1.w, w3, acc[7]);
    }
    #pragma unroll
    for (int off = 16; off > 0; off >>= 1) {
        #pragma unroll
        for (int o = 0; o < 8; o++) acc[o] += __shfl_xor_sync(0xffffffffu, acc[o], off);
        #pragma unroll
        for (int h = 0; h < 4; h++) den[h] += __shfl_xor_sync(0xffffffffu, den[h], off);
    }
    if (lane == 0) {
        bool has = end > beg;
        float o0 = 0.f, o1 = 0.f;
        #pragma unroll
        for (int h = 0; h < 4; h++) {
            float r0 = has ? acc[2 * h] / den[h] : 0.f;
            float r1 = has ? acc[2 * h + 1] / den[h] : 0.f;
            r0 += r4[n * 8 + 2 * h] + b4[2 * h];
            r1 += r4[n * 8 + 2 * h + 1] + b4[2 * h + 1];
            float m = fmaxf(r0, r1);
            float e0 = expf(r0 - m), e1 = expf(r1 - m);
            float s = e0 + e1;
            o0 += e0 / s;
            o1 += e1 / s;
        }
        out[n * 2 + 0] = o0 * 0.25f;
        out[n * 2 + 1] = o1 * 0.25f;
    }
}

// ---------------- host launcher ----------------------------------------------
extern "C" void kernel_launch(void* const* d_in, const int* in_sizes, int n_in,
                              void* d_out, int out_size) {
    const float* x     = (const float*)d_in[0];
    const int*   src   = (const int*)  d_in[1];
    const int*   dst   = (const int*)  d_in[2];
    const float* W1    = (const float*)d_in[3];
    const float* al1   = (const float*)d_in[4];
    const float* ar1   = (const float*)d_in[5];
    const float* b1    = (const float*)d_in[6];
    const float* W2    = (const float*)d_in[7];
    const float* al2   = (const float*)d_in[8];
    const float* ar2   = (const float*)d_in[9];
    const float* b2    = (const float*)d_in[10];
    const float* W3    = (const float*)d_in[11];
    const float* al3   = (const float*)d_in[12];
    const float* ar3   = (const float*)d_in[13];
    const float* b3    = (const float*)d_in[14];
    const float* W4    = (const float*)d_in[15];
    const float* al4   = (const float*)d_in[16];
    const float* ar4   = (const float*)d_in[17];
    const float* b4    = (const float*)d_in[18];
    const float* resW4 = (const float*)d_in[19];
    float* out = (float*)d_out;
    const int E = in_sizes[1];

    __half *feath, *xh, *hAh, *hBh, *W1h, *W2h, *W3h;
    float *el, *er, *f4, *r4;
    int *cnt, *rowptr, *cur, *csrc;
    cudaGetSymbolAddress((void**)&feath,  g_feath);
    cudaGetSymbolAddress((void**)&xh,     g_xh);
    cudaGetSymbolAddress((void**)&hAh,    g_hAh);
    cudaGetSymbolAddress((void**)&hBh,    g_hBh);
    cudaGetSymbolAddress((void**)&W1h,    g_W1h);
    cudaGetSymbolAddress((void**)&W2h,    g_W2h);
    cudaGetSymbolAddress((void**)&W3h,    g_W3h);
    cudaGetSymbolAddress((void**)&el,     g_el);
    cudaGetSymbolAddress((void**)&er,     g_er);
    cudaGetSymbolAddress((void**)&f4,     g_f4);
    cudaGetSymbolAddress((void**)&r4,     g_r4);
    cudaGetSymbolAddress((void**)&cnt,    g_cnt);
    cudaGetSymbolAddress((void**)&rowptr, g_rowptr);
    cudaGetSymbolAddress((void**)&cur,    g_cur);
    cudaGetSymbolAddress((void**)&csrc,   g_csrc);

    cudaFuncSetAttribute(k_gemm_fp16,
                         cudaFuncAttributeMaxDynamicSharedMemorySize, GEMM_SMEM);

    // ---- converts ----
    const int xn4 = NN * 128 / 4;
    k_cvtAll<<<(xn4 + 255) / 256, 256>>>((const float4*)x, (uint2*)xh, xn4,
                                         (const float4*)W1, (uint2*)W1h,
                                         (const float4*)W2, (uint2*)W2h,
                                         (const float4*)W3, (uint2*)W3h);

    // ---- CSR by dst (R10-proven 3-kernel scan) ----
    k_zero_cnt<<<(NN + 255) / 256, 256>>>(cnt);
    k_histo<<<1024, 256>>>(dst, cnt, E);
    k_scan_part<<<NB, 1024>>>(cnt);
    k_scan_small<<<1, 64>>>(rowptr);
    k_scan_final<<<NB, 1024>>>(cnt, rowptr, cur);
    k_scatter<<<1024, 256>>>(src, dst, cur, csrc, E);

    dim3 gemm_grid(FD / BN, (NN + BM - 1) / BM);   // (2, 391)
    const int agg_grid = (NN + 3) / 4;

    // ---- layer 1 ----
    k_gemm_fp16<<<gemm_grid, 256, GEMM_SMEM>>>(xh, W1h, feath, al1, ar1, el, er, NN, 128);
    k_edge_agg<<<agg_grid, 128>>>((const uint4*)feath, (const float4*)el,
                                  (const float4*)er, rowptr, csrc, nullptr,
                                  (const float4*)b1, (uint4*)hAh);

    // ---- layer 2 ----
    k_gemm_fp16<<<gemm_grid, 256, GEMM_SMEM>>>(hAh, W2h, feath, al2, ar2, el, er, NN, FD);
    k_edge_agg<<<agg_grid, 128>>>((const uint4*)feath, (const float4*)el,
                                  (const float4*)er, rowptr, csrc,
                                  (const uint4*)hAh, (const float4*)b2, (uint4*)hBh);

    // ---- layer 3 ----
    k_gemm_fp16<<<gemm_grid, 256, GEMM_SMEM>>>(hBh, W3h, feath, al3, ar3, el, er, NN, FD);
    k_edge_agg<<<agg_grid, 128>>>((const uint4*)feath, (const float4*)el,
                                  (const float4*)er, rowptr, csrc,
                                  (const uint4*)hBh, (const float4*)b3, (uint4*)hAh);

    // ---- layer 4 ----
    k_l4_proj<<<(NN + 7) / 8, 256>>>(hAh, W4, resW4, al4, ar4, f4, r4, el, er);
    k_l4_edge<<<(NN + 7) / 8, 256>>>(f4, el, er, rowptr, csrc, r4, b4, out);
}

// round 14
// speedup vs baseline: 1.6819x; 1.0153x over previous
#include <cuda_runtime.h>
#include <cuda_fp16.h>
#include <cstdint>
#include <cstring>

#define NN 50000
#define EE 800000
#define FD 256          // H*HID
#define NEG 0.2f
#define NB 49           // ceil(NN/1024)

__device__ __forceinline__ uint32_t h2_as_u32(__half2 v) {
    uint32_t u;
    memcpy(&u, &v, 4);
    return u;
}

// ---------------- scratch (device globals; no allocation allowed) ------------
__device__ __half g_feath[(size_t)NN * FD];   // fp16 post-GEMM features
__device__ __half g_xh[(size_t)NN * 128];     // fp16 input x
__device__ __half g_hAh[(size_t)NN * FD];     // fp16 h ping
__device__ __half g_hBh[(size_t)NN * FD];     // fp16 h pong
__device__ __half g_W1h[256 * 128];
__device__ __half g_W2h[256 * 256];
__device__ __half g_W3h[256 * 256];
__device__ float g_el[NN * 4];
__device__ float g_er[NN * 4];
__device__ float g_f4[NN * 8];
__device__ float g_r4[NN * 8];
__device__ int   g_cnt[NN];
__device__ int   g_rowptr[NN + 1];
__device__ int   g_cur[NN];
__device__ int   g_csrc[EE];
__device__ int   g_bsum[64];

// ---------------- merged converts (x + W1..W3) + cnt zeroing -----------------
__global__ void k_cvtAll(const float4* __restrict__ x, uint2* __restrict__ xo, int xn4,
                         const float4* __restrict__ w1, uint2* __restrict__ o1,
                         const float4* __restrict__ w2, uint2* __restrict__ o2,
                         const float4* __restrict__ w3, uint2* __restrict__ o3,
                         int* __restrict__ cnt) {
    int i = blockIdx.x * blockDim.x + threadIdx.x;
    if (i < NN) cnt[i] = 0;
    if (i < xn4) {
        float4 v = x[i];
        xo[i] = make_uint2(h2_as_u32(__floats2half2_rn(v.x, v.y)),
                           h2_as_u32(__floats2half2_rn(v.z, v.w)));
    }
    if (i < 8192) {
        float4 v = w1[i];
        o1[i] = make_uint2(h2_as_u32(__floats2half2_rn(v.x, v.y)),
                           h2_as_u32(__floats2half2_rn(v.z, v.w)));
    }
    if (i < 16384) {
        float4 v = w2[i];
        o2[i] = make_uint2(h2_as_u32(__floats2half2_rn(v.x, v.y)),
                           h2_as_u32(__floats2half2_rn(v.z, v.w)));
        float4 u = w3[i];
        o3[i] = make_uint2(h2_as_u32(__floats2half2_rn(u.x, u.y)),
                           h2_as_u32(__floats2half2_rn(u.z, u.w)));
    }
}

// ---------------- CSR build --------------------------------------------------
__global__ void k_histo(const int* __restrict__ dst, int* __restrict__ cnt, int E) {
    for (int i = blockIdx.x * blockDim.x + threadIdx.x; i < E; i += gridDim.x * blockDim.x)
        atomicAdd(&cnt[dst[i]], 1);
}

__global__ void k_scan_part(const int* __restrict__ cnt) {
    __shared__ int sh[1024];
    int i = blockIdx.x * 1024 + threadIdx.x;
    sh[threadIdx.x] = (i < NN) ? cnt[i] : 0;
    __syncthreads();
    for (int o = 512; o > 0; o >>= 1) {
        if (threadIdx.x < o) sh[threadIdx.x] += sh[threadIdx.x + o];
        __syncthreads();
    }
    if (threadIdx.x == 0) g_bsum[blockIdx.x] = sh[0];
}

__global__ void k_scan_small(int* rowptr) {
    __shared__ int sh[64];
    int t = threadIdx.x;
    int v = (t < NB) ? g_bsum[t] : 0;
    sh[t] = v;
    __syncthreads();
    #pragma unroll
    for (int o = 1; o < 64; o <<= 1) {
        int u = (t >= o) ? sh[t - o] : 0;
        __syncthreads();
        sh[t] += u;
        __syncthreads();
    }
    if (t < NB) g_bsum[t] = sh[t] - v;       // exclusive prefix
    if (t == 63) rowptr[NN] = sh[63];
}

__global__ void k_scan_final(const int* __restrict__ cnt, int* __restrict__ rowptr,
                             int* __restrict__ cur) {
    __shared__ int sh[1024];
    int tid = threadIdx.x;
    int i = blockIdx.x * 1024 + tid;
    int v = (i < NN) ? cnt[i] : 0;
    sh[tid] = v;
    __syncthreads();
    #pragma unroll
    for (int o = 1; o < 1024; o <<= 1) {
        int t = (tid >= o) ? sh[tid - o] : 0;
        __syncthreads();
        sh[tid] += t;
        __syncthreads();
    }
    if (i < NN) { int ex = g_bsum[blockIdx.x] + sh[tid] - v; rowptr[i] = ex; cur[i] = ex; }
}

__global__ void k_scatter(const int* __restrict__ src, const int* __restrict__ dst,
                          int* __restrict__ cur, int* __restrict__ csrc, int E) {
    for (int i = blockIdx.x * blockDim.x + threadIdx.x; i < E; i += gridDim.x * blockDim.x) {
        int d = dst[i];
        int p = atomicAdd(&cur[d], 1);
        csrc[p] = src[i];
    }
}

// ---------------- fp16 GEMM BN=128 (cp.async dbuf, LDSM frags) + el/er -------
#define BM 128
#define BN 128
#define BKB 64                    // fp16 k per stage
#define BKBP 72                   // +8 pad: LDSM row offsets distinct mod 128B
#define ASZB (BM * BKBP)
#define BSZB (BN * BKBP)
#define GEMM_SMEM ((2 * (ASZB + BSZB)) * (int)sizeof(__half))   // 73728 B

__device__ __forceinline__ void cp16(uint32_t s, const void* g) {
    asm volatile("cp.async.cg.shared.global [%0], [%1], 16;" :: "r"(s), "l"(g));
}

__device__ __forceinline__ void ldsm4(uint32_t (&r)[4], uint32_t saddr) {
    asm volatile("ldmatrix.sync.aligned.m8n8.x4.shared.b16 {%0,%1,%2,%3}, [%4];"
                 : "=r"(r[0]), "=r"(r[1]), "=r"(r[2]), "=r"(r[3]) : "r"(saddr));
}

__device__ __forceinline__ void mma_fp16(float (&d)[4], const uint32_t (&a)[4],
                                         const uint32_t b0, const uint32_t b1) {
    asm volatile(
        "mma.sync.aligned.m16n8k16.row.col.f32.f16.f16.f32 "
        "{%0,%1,%2,%3},{%4,%5,%6,%7},{%8,%9},{%0,%1,%2,%3};"
        : "+f"(d[0]), "+f"(d[1]), "+f"(d[2]), "+f"(d[3])
        : "r"(a[0]), "r"(a[1]), "r"(a[2]), "r"(a[3]), "r"(b0), "r"(b1));
}

__global__ void __launch_bounds__(256) k_gemm_fp16(
        const __half* __restrict__ A, const __half* __restrict__ B,
        __half* __restrict__ C,
        const float* __restrict__ al, const float* __restrict__ ar,
        float* __restrict__ el, float* __restrict__ er, int M, int K) {
    extern __shared__ __half smem[];
    __half* Asm = smem;                 // [2][BM][BKBP]
    __half* Bsm = smem + 2 * ASZB;      // [2][BN][BKBP]
    __shared__ float sAl[BN], sAr[BN];

    const int bx = blockIdx.x;
    const int bm = blockIdx.y * BM, bn = bx * BN;
    const int tid = threadIdx.x;
    const int warp = tid >> 5, lane = tid & 31;
    const int wm = warp & 3, wn = warp >> 2;      // wn in {0,1}: head within block
    const int r = lane >> 2, c = lane & 3;
    const int hg = bx * 2 + wn;

    if (tid < BN) { sAl[tid] = al[bn + tid]; sAr[tid] = ar[bn + tid]; }

    const int lrow = tid >> 1, lcol = (tid & 1) * 32;
    const bool aok = (bm + lrow) < M;

    // LDSM lane addressing: tile = lane>>3, tr = lane&7
    const int ltile = lane >> 3, ltr = lane & 7;
    // A: tiles {rows+0..7 klo, rows+8..15 klo, rows+0..7 khi, rows+8..15 khi}
    const int a_row_off = (ltile & 1) * 8 + ltr;       // +0/+8 rows
    const int a_k_off   = (ltile >> 1) * 8;            // +0/+8 k
    // B: tiles {n+0..7 klo, n+0..7 khi, n+8..15 klo, n+8..15 khi}
    const int b_row_off = (ltile >> 1) * 8 + ltr;      // +0/+8 n
    const int b_k_off   = (ltile & 1) * 8;             // +0/+8 k

    float acc[2][8][4];
    #pragma unroll
    for (int mt = 0; mt < 2; mt++)
        #pragma unroll
        for (int nt = 0; nt < 8; nt++)
            #pragma unroll
            for (int i = 0; i < 4; i++) acc[mt][nt][i] = 0.f;

    const int ntile = K / BKB;

    auto issue = [&](int buf, int kt) {
        if (aok) {
            uint32_t sa = (uint32_t)__cvta_generic_to_shared(
                &Asm[(buf * BM + lrow) * BKBP + lcol]);
            const __half* ga = &A[(size_t)(bm + lrow) * K + kt + lcol];
            #pragma unroll
            for (int j = 0; j < 4; j++) cp16(sa + j * 16, ga + j * 8);
        }
        uint32_t sb = (uint32_t)__cvta_generic_to_shared(
            &Bsm[(buf * BN + lrow) * BKBP + lcol]);
        const __half* gb = &B[(size_t)(bn + lrow) * K + kt + lcol];
        #pragma unroll
        for (int j = 0; j < 4; j++) cp16(sb + j * 16, gb + j * 8);
    };

    issue(0, 0);
    asm volatile("cp.async.commit_group;");

    for (int t = 0; t < ntile; t++) {
        if (t + 1 < ntile) {
            issue((t + 1) & 1, (t + 1) * BKB);
            asm volatile("cp.async.commit_group;");
            asm volatile("cp.async.wait_group 1;");
        } else {
            asm volatile("cp.async.wait_group 0;");
        }
        __syncthreads();
        const __half* Ab = &Asm[((t & 1) * BM) * BKBP];
        const __half* Bb = &Bsm[((t & 1) * BN) * BKBP];
        uint32_t abase = (uint32_t)__cvta_generic_to_shared(Ab);
        uint32_t bbase = (uint32_t)__cvta_generic_to_shared(Bb);
        #pragma unroll
        for (int kk = 0; kk < BKB; kk += 16) {
            uint32_t af[2][4], bf[4][4];
            #pragma unroll
            for (int mt = 0; mt < 2; mt++) {
                int row0 = wm * 32 + mt * 16;
                uint32_t addr = abase +
                    ((row0 + a_row_off) * BKBP + kk + a_k_off) * 2;
                ldsm4(af[mt], addr);
            }
            #pragma unroll
            for (int np = 0; np < 4; np++) {          // pair of n-tiles
                int n0 = wn * 64 + np * 16;
                uint32_t addr = bbase +
                    ((n0 + b_row_off) * BKBP + kk + b_k_off) * 2;
                ldsm4(bf[np], addr);                  // {b0(nt0),b1(nt0),b0(nt1),b1(nt1)}
            }
            #pragma unroll
            for (int mt = 0; mt < 2; mt++)
                #pragma unroll
                for (int np = 0; np < 4; np++) {
                    mma_fp16(acc[mt][np * 2],     af[mt], bf[np][0], bf[np][1]);
                    mma_fp16(acc[mt][np * 2 + 1], af[mt], bf[np][2], bf[np][3]);
                }
        }
        __syncthreads();
    }

    // ---- store fp16 feat ----
    #pragma unroll
    for (int mt = 0; mt < 2; mt++) {
        #pragma unroll
        for (int nt = 0; nt < 8; nt++) {
            int row = bm + wm * 32 + mt * 16 + r;
            int col = bn + wn * 64 + nt * 8 + 2 * c;
            if (row < M)
                *(__half2*)&C[(size_t)row * FD + col] =
                    __floats2half2_rn(acc[mt][nt][0], acc[mt][nt][1]);
            if (row + 8 < M)
                *(__half2*)&C[(size_t)(row + 8) * FD + col] =
                    __floats2half2_rn(acc[mt][nt][2], acc[mt][nt][3]);
        }
    }

    // ---- fused el/er: warp owns (rows wm*32..+31, head hg); direct write ----
    #pragma unroll
    for (int mt = 0; mt < 2; mt++) {
        #pragma unroll
        for (int rh = 0; rh < 2; rh++) {
            float se = 0.f, sr2 = 0.f;
            #pragma unroll
            for (int nt = 0; nt < 8; nt++) {
                int col = wn * 64 + nt * 8 + 2 * c;
                float a0 = acc[mt][nt][rh * 2], a1 = acc[mt][nt][rh * 2 + 1];
                se  += a0 * sAl[col] + a1 * sAl[col + 1];
                sr2 += a0 * sAr[col] + a1 * sAr[col + 1];
            }
            se  += __shfl_xor_sync(0xffffffffu, se, 1);
            se  += __shfl_xor_sync(0xffffffffu, se, 2);
            sr2 += __shfl_xor_sync(0xffffffffu, sr2, 1);
            sr2 += __shfl_xor_sync(0xffffffffu, sr2, 2);
            if (c == 0) {
                int row = bm + wm * 32 + mt * 16 + rh * 8 + r;
                if (row < M) {
                    el[row * 4 + hg] = se;
                    er[row * 4 + hg] = sr2;
                }
            }
        }
    }
}

// ---------------- fused edge aggregation: warp per node, fp16 everywhere -----
__global__ void __launch_bounds__(128) k_edge_agg(
        const uint4* __restrict__ feath,      // [N][32] x (8 fp16)
        const float4* __restrict__ el4, const float4* __restrict__ er4,
        const int* __restrict__ rowptr, const int* __restrict__ csrc,
        const uint4* __restrict__ hprevh,     // fp16 prev h or null
        const float4* __restrict__ bias4,
        uint4* __restrict__ houth) {          // fp16 out h
    int w = threadIdx.x >> 5;
    int n = blockIdx.x * 4 + w;
    int lane = threadIdx.x & 31;
    if (n >= NN) return;
    int head = lane >> 3;
    __shared__ int   ssrc[4][32];
    __shared__ float sw[4][32][4];
    int beg = rowptr[n], end = rowptr[n + 1];
    float4 erd = er4[n];
    float acc[8];
    #pragma unroll
    for (int i = 0; i < 8; i++) acc[i] = 0.f;
    float4 dl = make_float4(0.f, 0.f, 0.f, 0.f);

    #define ACCUM(fv, wgt) do {                                             \
        const __half2* _p = (const __half2*)&(fv);                          \
        _Pragma("unroll")                                                   \
        for (int _j = 0; _j < 4; _j++) {                                    \
            float2 _v = __half22float2(_p[_j]);                             \
            acc[2 * _j]     = fmaf(_v.x, (wgt), acc[2 * _j]);               \
            acc[2 * _j + 1] = fmaf(_v.y, (wgt), acc[2 * _j + 1]);           \
        } } while (0)

    for (int base = beg; base < end; base += 32) {
        int cnt = min(32, end - base);
        if (lane < cnt) {
            int s = csrc[base + lane];
            ssrc[w][lane] = s;
            float4 le = el4[s];
            float x0 = le.x + erd.x; x0 = x0 > 0.f ? x0 : NEG * x0;
            float x1 = le.y + erd.y; x1 = x1 > 0.f ? x1 : NEG * x1;
            float x2 = le.z + erd.z; x2 = x2 > 0.f ? x2 : NEG * x2;
            float x3 = le.w + erd.w; x3 = x3 > 0.f ? x3 : NEG * x3;
            float w0 = expf(x0), w1 = expf(x1), w2 = expf(x2), w3 = expf(x3);
            sw[w][lane][0] = w0; sw[w][lane][1] = w1;
            sw[w][lane][2] = w2; sw[w][lane][3] = w3;
            dl.x += w0; dl.y += w1; dl.z += w2; dl.w += w3;
        }
        __syncwarp();
        int e = 0;
        for (; e + 4 <= cnt; e += 4) {
            uint4 f0 = feath[(size_t)ssrc[w][e]     * 32 + lane];
            uint4 f1 = feath[(size_t)ssrc[w][e + 1] * 32 + lane];
            uint4 f2 = feath[(size_t)ssrc[w][e + 2] * 32 + lane];
            uint4 f3 = feath[(size_t)ssrc[w][e + 3] * 32 + lane];
            float w0 = sw[w][e][head],     w1 = sw[w][e + 1][head];
            float w2 = sw[w][e + 2][head], w3 = sw[w][e + 3][head];
            ACCUM(f0, w0); ACCUM(f1, w1); ACCUM(f2, w2); ACCUM(f3, w3);
        }
        for (; e < cnt; e++) {
            uint4 fv = feath[(size_t)ssrc[w][e] * 32 + lane];
            float wg = sw[w][e][head];
            ACCUM(fv, wg);
        }
        __syncwarp();
    }
    #undef ACCUM

    #pragma unroll
    for (int o = 16; o > 0; o >>= 1) {
        dl.x += __shfl_xor_sync(0xffffffffu, dl.x, o);
        dl.y += __shfl_xor_sync(0xffffffffu, dl.y, o);
        dl.z += __shfl_xor_sync(0xffffffffu, dl.z, o);
        dl.w += __shfl_xor_sync(0xffffffffu, dl.w, o);
    }
    float den = (head == 0) ? dl.x : (head == 1) ? dl.y : (head == 2) ? dl.z : dl.w;
    float inv = (end > beg) ? 1.f / den : 0.f;
    float4 b0 = bias4[lane * 2], b1 = bias4[lane * 2 + 1];
    float v[8];
    v[0] = acc[0] * inv + b0.x; v[1] = acc[1] * inv + b0.y;
    v[2] = acc[2] * inv + b0.z; v[3] = acc[3] * inv + b0.w;
    v[4] = acc[4] * inv + b1.x; v[5] = acc[5] * inv + b1.y;
    v[6] = acc[6] * inv + b1.z; v[7] = acc[7] * inv + b1.w;
    if (hprevh) {
        uint4 pv = hprevh[(size_t)n * 32 + lane];
        const __half2* pp = (const __half2*)&pv;
        #pragma unroll
        for (int j = 0; j < 4; j++) {
            float2 p = __half22float2(pp[j]);
            v[2 * j]     += p.x;
            v[2 * j + 1] += p.y;
        }
    }
    #pragma unroll
    for (int j = 0; j < 8; j++)
        v[j] = v[j] > 0.f ? v[j] : expm1f(v[j]);
    uint4 ob;
    ob.x = h2_as_u32(__floats2half2_rn(v[0], v[1]));
    ob.y = h2_as_u32(__floats2half2_rn(v[2], v[3]));
    ob.z = h2_as_u32(__floats2half2_rn(v[4], v[5]));
    ob.w = h2_as_u32(__floats2half2_rn(v[6], v[7]));
    houth[(size_t)n * 32 + lane] = ob;
}

// ---------------- layer-4 projection + el/er (merged, fp16 h) ----------------
__global__ void k_l4_proj(const __half* __restrict__ h, const float* __restrict__ W4,
                          const float* __restrict__ rW4,
                          const float* __restrict__ al4, const float* __restrict__ ar4,
                          float* __restrict__ f4, float* __restrict__ r4,
                          float* __restrict__ el, float* __restrict__ er) {
    int n = blockIdx.x * 8 + (threadIdx.x >> 5);
    int lane = threadIdx.x & 31;
    if (n >= NN) return;
    float acc[16];
    #pragma unroll
    for (int o = 0; o < 16; o++) acc[o] = 0.f;
    const __half* hr = h + (size_t)n * FD;
    #pragma unroll
    for (int k8 = 0; k8 < 8; k8++) {
        int k = k8 * 32 + lane;
        float hv = __half2float(hr[k]);
        #pragma unroll
        for (int o = 0; o < 8; o++) acc[o]     = fmaf(hv, W4[o * FD + k], acc[o]);
        #pragma unroll
        for (int o = 0; o < 8; o++) acc[8 + o] = fmaf(hv, rW4[o * FD + k], acc[8 + o]);
    }
    #pragma unroll
    for (int o = 0; o < 16; o++)
        #pragma unroll
        for (int off = 16; off > 0; off >>= 1)
            acc[o] += __shfl_xor_sync(0xffffffffu, acc[o], off);
    if (lane < 8) {
        f4[n * 8 + lane] = acc[lane];
        r4[n * 8 + lane] = acc[8 + lane];
    }
    if (lane < 4) {
        el[n * 4 + lane] = acc[2 * lane] * al4[2 * lane] +
                           acc[2 * lane + 1] * al4[2 * lane + 1];
        er[n * 4 + lane] = acc[2 * lane] * ar4[2 * lane] +
                           acc[2 * lane + 1] * ar4[2 * lane + 1];
    }
}

// ---------------- layer-4 edge agg + softmax + head-mean ---------------------
__global__ void k_l4_edge(const float* __restrict__ f4, const float* __restrict__ el,
                          const float* __restrict__ er, const int* __restrict__ rowptr,
                          const int* __restrict__ csrc, const float* __restrict__ r4,
                          const float* __restrict__ b4, float* __restrict__ out) {
    int n = blockIdx.x * 8 + (threadIdx.x >> 5);
    int lane = threadIdx.x & 31;
    if (n >= NN) return;
    int beg = rowptr[n], end = rowptr[n + 1];
    float4 erd = ((const float4*)er)[n];
    float acc[8] = {0, 0, 0, 0, 0, 0, 0, 0};
    float den[4] = {0, 0, 0, 0};
    for (int e = beg + lane; e < end; e += 32) {
        int s = csrc[e];
        float4 le = ((const float4*)el)[s];
        float x0 = le.x + erd.x; x0 = x0 > 0.f ? x0 : NEG * x0;
        float x1 = le.y + erd.y; x1 = x1 > 0.f ? x1 : NEG * x1;
        float x2 = le.z + erd.z; x2 = x2 > 0.f ? x2 : NEG * x2;
        float x3 = le.w + erd.w; x3 = x3 > 0.f ? x3 : NEG * x3;
        float w0 = expf(x0), w1 = expf(x1), w2 = expf(x2), w3 = expf(x3);
        den[0] += w0; den[1] += w1; den[2] += w2; den[3] += w3;
        float4 f0 = ((const float4*)f4)[s * 2];
        float4 f1 = ((const float4*)f4)[s * 2 + 1];
        acc[0] = fmaf(f0.x, w0, acc[0]);  acc[1] = fmaf(f0.y, w0, acc[1]);
        acc[2] = fmaf(f0.z, w1, acc[2]);  acc[3] = fmaf(f0.w, w1, acc[3]);
        acc[4] = fmaf(f1.x, w2, acc[4]);  acc[5] = fmaf(f1.y, w2, acc[5]);
        acc[6] = fmaf(f1.z, w3, acc[6]);  acc[7] = fmaf(f1.w, w3, acc[7]);
    }
    #pragma unroll
    for (int off = 16; off > 0; off >>= 1) {
        #pragma unroll
        for (int o = 0; o < 8; o++) acc[o] += __shfl_xor_sync(0xffffffffu, acc[o], off);
        #pragma unroll
        for (int h = 0; h < 4; h++) den[h] += __shfl_xor_sync(0xffffffffu, den[h], off);
    }
    if (lane == 0) {
        bool has = end > beg;
        float o0 = 0.f, o1 = 0.f;
        #pragma unroll
        for (int h = 0; h < 4; h++) {
            float r0 = has ? acc[2 * h] / den[h] : 0.f;
            float r1 = has ? acc[2 * h + 1] / den[h] : 0.f;
            r0 += r4[n * 8 + 2 * h] + b4[2 * h];
            r1 += r4[n * 8 + 2 * h + 1] + b4[2 * h + 1];
            float m = fmaxf(r0, r1);
            float e0 = expf(r0 - m), e1 = expf(r1 - m);
            float s = e0 + e1;
            o0 += e0 / s;
            o1 += e1 / s;
        }
        out[n * 2 + 0] = o0 * 0.25f;
        out[n * 2 + 1] = o1 * 0.25f;
    }
}

// ---------------- host launcher ----------------------------------------------
extern "C" void kernel_launch(void* const* d_in, const int* in_sizes, int n_in,
                              void* d_out, int out_size) {
    const float* x     = (const float*)d_in[0];
    const int*   src   = (const int*)  d_in[1];
    const int*   dst   = (const int*)  d_in[2];
    const float* W1    = (const float*)d_in[3];
    const float* al1   = (const float*)d_in[4];
    const float* ar1   = (const float*)d_in[5];
    const float* b1    = (const float*)d_in[6];
    const float* W2    = (const float*)d_in[7];
    const float* al2   = (const float*)d_in[8];
    const float* ar2   = (const float*)d_in[9];
    const float* b2    = (const float*)d_in[10];
    const float* W3    = (const float*)d_in[11];
    const float* al3   = (const float*)d_in[12];
    const float* ar3   = (const float*)d_in[13];
    const float* b3    = (const float*)d_in[14];
    const float* W4    = (const float*)d_in[15];
    const float* al4   = (const float*)d_in[16];
    const float* ar4   = (const float*)d_in[17];
    const float* b4    = (const float*)d_in[18];
    const float* resW4 = (const float*)d_in[19];
    float* out = (float*)d_out;
    const int E = in_sizes[1];

    __half *feath, *xh, *hAh, *hBh, *W1h, *W2h, *W3h;
    float *el, *er, *f4, *r4;
    int *cnt, *rowptr, *cur, *csrc;
    cudaGetSymbolAddress((void**)&feath,  g_feath);
    cudaGetSymbolAddress((void**)&xh,     g_xh);
    cudaGetSymbolAddress((void**)&hAh,    g_hAh);
    cudaGetSymbolAddress((void**)&hBh,    g_hBh);
    cudaGetSymbolAddress((void**)&W1h,    g_W1h);
    cudaGetSymbolAddress((void**)&W2h,    g_W2h);
    cudaGetSymbolAddress((void**)&W3h,    g_W3h);
    cudaGetSymbolAddress((void**)&el,     g_el);
    cudaGetSymbolAddress((void**)&er,     g_er);
    cudaGetSymbolAddress((void**)&f4,     g_f4);
    cudaGetSymbolAddress((void**)&r4,     g_r4);
    cudaGetSymbolAddress((void**)&cnt,    g_cnt);
    cudaGetSymbolAddress((void**)&rowptr, g_rowptr);
    cudaGetSymbolAddress((void**)&cur,    g_cur);
    cudaGetSymbolAddress((void**)&csrc,   g_csrc);

    cudaFuncSetAttribute(k_gemm_fp16,
                         cudaFuncAttributeMaxDynamicSharedMemorySize, GEMM_SMEM);

    // ---- converts + cnt zeroing ----
    const int xn4 = NN * 128 / 4;
    k_cvtAll<<<(xn4 + 255) / 256, 256>>>((const float4*)x, (uint2*)xh, xn4,
                                         (const float4*)W1, (uint2*)W1h,
                                         (const float4*)W2, (uint2*)W2h,
                                         (const float4*)W3, (uint2*)W3h, cnt);

    // ---- CSR by dst ----
    k_histo<<<1024, 256>>>(dst, cnt, E);
    k_scan_part<<<NB, 1024>>>(cnt);
    k_scan_small<<<1, 64>>>(rowptr);
    k_scan_final<<<NB, 1024>>>(cnt, rowptr, cur);
    k_scatter<<<1024, 256>>>(src, dst, cur, csrc, E);

    dim3 gemm_grid(FD / BN, (NN + BM - 1) / BM);   // (2, 391)
    const int agg_grid = (NN + 3) / 4;

    // ---- layer 1 ----
    k_gemm_fp16<<<gemm_grid, 256, GEMM_SMEM>>>(xh, W1h, feath, al1, ar1, el, er, NN, 128);
    k_edge_agg<<<agg_grid, 128>>>((const uint4*)feath, (const float4*)el,
                                  (const float4*)er, rowptr, csrc, nullptr,
                                  (const float4*)b1, (uint4*)hAh);

    // ---- layer 2 ----
    k_gemm_fp16<<<gemm_grid, 256, GEMM_SMEM>>>(hAh, W2h, feath, al2, ar2, el, er, NN, FD);
    k_edge_agg<<<agg_grid, 128>>>((const uint4*)feath, (const float4*)el,
                                  (const float4*)er, rowptr, csrc,
                                  (const uint4*)hAh, (const float4*)b2, (uint4*)hBh);

    // ---- layer 3 ----
    k_gemm_fp16<<<gemm_grid, 256, GEMM_SMEM>>>(hBh, W3h, feath, al3, ar3, el, er, NN, FD);
    k_edge_agg<<<agg_grid, 128>>>((const uint4*)feath, (const float4*)el,
                                  (const float4*)er, rowptr, csrc,
                                  (const uint4*)hBh, (const float4*)b3, (uint4*)hAh);

    // ---- layer 4 ----
    k_l4_proj<<<(NN + 7) / 8, 256>>>(hAh, W4, resW4, al4, ar4, f4, r4, el, er);
    k_l4_edge<<<(NN + 7) / 8, 256>>>(f4, el, er, rowptr, csrc, r4, b4, out);
}

// round 16
// speedup vs baseline: 1.7274x; 1.0270x over previous
#include <cuda_runtime.h>
#include <cuda_fp16.h>
#include <cstdint>
#include <cstring>

#define NN 50000
#define EE 800000
#define FD 256          // H*HID
#define NEG 0.2f
#define NB 49           // ceil(NN/1024)

__device__ __forceinline__ uint32_t h2_as_u32(__half2 v) {
    uint32_t u;
    memcpy(&u, &v, 4);
    return u;
}

// ---------------- scratch (device globals; no allocation allowed) ------------
__device__ __half g_feath[(size_t)NN * FD];   // fp16 post-GEMM features
__device__ __half g_xh[(size_t)NN * 128];     // fp16 input x
__device__ __half g_hAh[(size_t)NN * FD];     // fp16 h ping
__device__ __half g_hBh[(size_t)NN * FD];     // fp16 h pong
__device__ __half g_W1h[256 * 128];
__device__ __half g_W2h[256 * 256];
__device__ __half g_W3h[256 * 256];
__device__ float g_el[NN * 4];
__device__ float g_er[NN * 4];
__device__ float g_f4[NN * 8];
__device__ float g_r4[NN * 8];
__device__ int   g_cnt[NN];
__device__ int   g_rowptr[NN + 1];
__device__ int   g_cur[NN];
__device__ int   g_csrc[EE];
__device__ int   g_bsum[64];

// ---------------- merged converts (x + W1..W3) + cnt zeroing -----------------
__global__ void k_cvtAll(const float4* __restrict__ x, uint2* __restrict__ xo, int xn4,
                         const float4* __restrict__ w1, uint2* __restrict__ o1,
                         const float4* __restrict__ w2, uint2* __restrict__ o2,
                         const float4* __restrict__ w3, uint2* __restrict__ o3,
                         int* __restrict__ cnt) {
    int i = blockIdx.x * blockDim.x + threadIdx.x;
    if (i < NN) cnt[i] = 0;
    if (i < xn4) {
        float4 v = x[i];
        xo[i] = make_uint2(h2_as_u32(__floats2half2_rn(v.x, v.y)),
                           h2_as_u32(__floats2half2_rn(v.z, v.w)));
    }
    if (i < 8192) {
        float4 v = w1[i];
        o1[i] = make_uint2(h2_as_u32(__floats2half2_rn(v.x, v.y)),
                           h2_as_u32(__floats2half2_rn(v.z, v.w)));
    }
    if (i < 16384) {
        float4 v = w2[i];
        o2[i] = make_uint2(h2_as_u32(__floats2half2_rn(v.x, v.y)),
                           h2_as_u32(__floats2half2_rn(v.z, v.w)));
        float4 u = w3[i];
        o3[i] = make_uint2(h2_as_u32(__floats2half2_rn(u.x, u.y)),
                           h2_as_u32(__floats2half2_rn(u.z, u.w)));
    }
}

// ---------------- CSR build --------------------------------------------------
__global__ void k_histo(const int* __restrict__ dst, int* __restrict__ cnt, int E) {
    for (int i = blockIdx.x * blockDim.x + threadIdx.x; i < E; i += gridDim.x * blockDim.x)
        atomicAdd(&cnt[dst[i]], 1);
}

__global__ void k_scan_part(const int* __restrict__ cnt) {
    __shared__ int sh[1024];
    int i = blockIdx.x * 1024 + threadIdx.x;
    sh[threadIdx.x] = (i < NN) ? cnt[i] : 0;
    __syncthreads();
    for (int o = 512; o > 0; o >>= 1) {
        if (threadIdx.x < o) sh[threadIdx.x] += sh[threadIdx.x + o];
        __syncthreads();
    }
    if (threadIdx.x == 0) g_bsum[blockIdx.x] = sh[0];
}

// per-block inclusive scan; offset = sum of g_bsum[0..bid-1] computed by warp 0
__global__ void k_scan_final(const int* __restrict__ cnt, int* __restrict__ rowptr,
                             int* __restrict__ cur) {
    __shared__ int sh[1024];
    __shared__ int s_off;
    int tid = threadIdx.x;
    int bid = blockIdx.x;
    if (tid < 32) {
        int s = 0;
        if (tid < bid) s += g_bsum[tid];
        if (tid + 32 < bid) s += g_bsum[tid + 32];
        #pragma unroll
        for (int o = 16; o > 0; o >>= 1) s += __shfl_xor_sync(0xffffffffu, s, o);
        if (tid == 0) s_off = s;
    }
    int i = bid * 1024 + tid;
    int v = (i < NN) ? cnt[i] : 0;
    sh[tid] = v;
    __syncthreads();
    #pragma unroll
    for (int o = 1; o < 1024; o <<= 1) {
        int t = (tid >= o) ? sh[tid - o] : 0;
        __syncthreads();
        sh[tid] += t;
        __syncthreads();
    }
    int off = s_off;
    if (i < NN) { int ex = off + sh[tid] - v; rowptr[i] = ex; cur[i] = ex; }
    if (bid == NB - 1 && tid == 1023) rowptr[NN] = off + sh[1023];
}

__global__ void k_scatter(const int* __restrict__ src, const int* __restrict__ dst,
                          int* __restrict__ cur, int* __restrict__ csrc, int E) {
    for (int i = blockIdx.x * blockDim.x + threadIdx.x; i < E; i += gridDim.x * blockDim.x) {
        int d = dst[i];
        int p = atomicAdd(&cur[d], 1);
        csrc[p] = src[i];
    }
}

// ---------------- fp16 GEMM BN=128 (cp.async dbuf, LDSM frags) + el/er -------
#define BM 128
#define BN 128
#define BKB 64                    // fp16 k per stage
#define BKBP 72                   // +8 pad: LDSM row offsets distinct mod 128B
#define ASZB (BM * BKBP)
#define BSZB (BN * BKBP)
#define GEMM_SMEM ((2 * (ASZB + BSZB)) * (int)sizeof(__half))   // 73728 B

__device__ __forceinline__ void cp16(uint32_t s, const void* g) {
    asm volatile("cp.async.cg.shared.global [%0], [%1], 16;" :: "r"(s), "l"(g));
}

__device__ __forceinline__ void ldsm4(uint32_t (&r)[4], uint32_t saddr) {
    asm volatile("ldmatrix.sync.aligned.m8n8.x4.shared.b16 {%0,%1,%2,%3}, [%4];"
                 : "=r"(r[0]), "=r"(r[1]), "=r"(r[2]), "=r"(r[3]) : "r"(saddr));
}

__device__ __forceinline__ void mma_fp16(float (&d)[4], const uint32_t (&a)[4],
                                         const uint32_t b0, const uint32_t b1) {
    asm volatile(
        "mma.sync.aligned.m16n8k16.row.col.f32.f16.f16.f32 "
        "{%0,%1,%2,%3},{%4,%5,%6,%7},{%8,%9},{%0,%1,%2,%3};"
        : "+f"(d[0]), "+f"(d[1]), "+f"(d[2]), "+f"(d[3])
        : "r"(a[0]), "r"(a[1]), "r"(a[2]), "r"(a[3]), "r"(b0), "r"(b1));
}

__global__ void __launch_bounds__(256) k_gemm_fp16(
        const __half* __restrict__ A, const __half* __restrict__ B,
        __half* __restrict__ C,
        const float* __restrict__ al, const float* __restrict__ ar,
        float* __restrict__ el, float* __restrict__ er, int M, int K) {
    extern __shared__ __half smem[];
    __half* Asm = smem;                 // [2][BM][BKBP]
    __half* Bsm = smem + 2 * ASZB;      // [2][BN][BKBP]
    __shared__ float sAl[BN], sAr[BN];

    const int bx = blockIdx.x;
    const int bm = blockIdx.y * BM, bn = bx * BN;
    const int tid = threadIdx.x;
    const int warp = tid >> 5, lane = tid & 31;
    const int wm = warp & 3, wn = warp >> 2;      // wn in {0,1}: head within block
    const int r = lane >> 2, c = lane & 3;
    const int hg = bx * 2 + wn;

    if (tid < BN) { sAl[tid] = al[bn + tid]; sAr[tid] = ar[bn + tid]; }

    const int lrow = tid >> 1, lcol = (tid & 1) * 32;
    const bool aok = (bm + lrow) < M;

    const int ltile = lane >> 3, ltr = lane & 7;
    const int a_row_off = (ltile & 1) * 8 + ltr;
    const int a_k_off   = (ltile >> 1) * 8;
    const int b_row_off = (ltile >> 1) * 8 + ltr;
    const int b_k_off   = (ltile & 1) * 8;

    float acc[2][8][4];
    #pragma unroll
    for (int mt = 0; mt < 2; mt++)
        #pragma unroll
        for (int nt = 0; nt < 8; nt++)
            #pragma unroll
            for (int i = 0; i < 4; i++) acc[mt][nt][i] = 0.f;

    const int ntile = K / BKB;

    auto issue = [&](int buf, int kt) {
        if (aok) {
            uint32_t sa = (uint32_t)__cvta_generic_to_shared(
                &Asm[(buf * BM + lrow) * BKBP + lcol]);
            const __half* ga = &A[(size_t)(bm + lrow) * K + kt + lcol];
            #pragma unroll
            for (int j = 0; j < 4; j++) cp16(sa + j * 16, ga + j * 8);
        }
        uint32_t sb = (uint32_t)__cvta_generic_to_shared(
            &Bsm[(buf * BN + lrow) * BKBP + lcol]);
        const __half* gb = &B[(size_t)(bn + lrow) * K + kt + lcol];
        #pragma unroll
        for (int j = 0; j < 4; j++) cp16(sb + j * 16, gb + j * 8);
    };

    issue(0, 0);
    asm volatile("cp.async.commit_group;");

    for (int t = 0; t < ntile; t++) {
        if (t + 1 < ntile) {
            issue((t + 1) & 1, (t + 1) * BKB);
            asm volatile("cp.async.commit_group;");
            asm volatile("cp.async.wait_group 1;");
        } else {
            asm volatile("cp.async.wait_group 0;");
        }
        __syncthreads();
        const __half* Ab = &Asm[((t & 1) * BM) * BKBP];
        const __half* Bb = &Bsm[((t & 1) * BN) * BKBP];
        uint32_t abase = (uint32_t)__cvta_generic_to_shared(Ab);
        uint32_t bbase = (uint32_t)__cvta_generic_to_shared(Bb);
        #pragma unroll
        for (int kk = 0; kk < BKB; kk += 16) {
            uint32_t af[2][4], bf[4][4];
            #pragma unroll
            for (int mt = 0; mt < 2; mt++) {
                int row0 = wm * 32 + mt * 16;
                uint32_t addr = abase +
                    ((row0 + a_row_off) * BKBP + kk + a_k_off) * 2;
                ldsm4(af[mt], addr);
            }
            #pragma unroll
            for (int np = 0; np < 4; np++) {
                int n0 = wn * 64 + np * 16;
                uint32_t addr = bbase +
                    ((n0 + b_row_off) * BKBP + kk + b_k_off) * 2;
                ldsm4(bf[np], addr);
            }
            #pragma unroll
            for (int mt = 0; mt < 2; mt++)
                #pragma unroll
                for (int np = 0; np < 4; np++) {
                    mma_fp16(acc[mt][np * 2],     af[mt], bf[np][0], bf[np][1]);
                    mma_fp16(acc[mt][np * 2 + 1], af[mt], bf[np][2], bf[np][3]);
                }
        }
        __syncthreads();
    }

    // ---- store fp16 feat ----
    #pragma unroll
    for (int mt = 0; mt < 2; mt++) {
        #pragma unroll
        for (int nt = 0; nt < 8; nt++) {
            int row = bm + wm * 32 + mt * 16 + r;
            int col = bn + wn * 64 + nt * 8 + 2 * c;
            if (row < M)
                *(__half2*)&C[(size_t)row * FD + col] =
                    __floats2half2_rn(acc[mt][nt][0], acc[mt][nt][1]);
            if (row + 8 < M)
                *(__half2*)&C[(size_t)(row + 8) * FD + col] =
                    __floats2half2_rn(acc[mt][nt][2], acc[mt][nt][3]);
        }
    }

    // ---- fused el/er ----
    #pragma unroll
    for (int mt = 0; mt < 2; mt++) {
        #pragma unroll
        for (int rh = 0; rh < 2; rh++) {
            float se = 0.f, sr2 = 0.f;
            #pragma unroll
            for (int nt = 0; nt < 8; nt++) {
                int col = wn * 64 + nt * 8 + 2 * c;
                float a0 = acc[mt][nt][rh * 2], a1 = acc[mt][nt][rh * 2 + 1];
                se  += a0 * sAl[col] + a1 * sAl[col + 1];
                sr2 += a0 * sAr[col] + a1 * sAr[col + 1];
            }
            se  += __shfl_xor_sync(0xffffffffu, se, 1);
            se  += __shfl_xor_sync(0xffffffffu, se, 2);
            sr2 += __shfl_xor_sync(0xffffffffu, sr2, 1);
            sr2 += __shfl_xor_sync(0xffffffffu, sr2, 2);
            if (c == 0) {
                int row = bm + wm * 32 + mt * 16 + rh * 8 + r;
                if (row < M) {
                    el[row * 4 + hg] = se;
                    er[row * 4 + hg] = sr2;
                }
            }
        }
    }
}

// ---------------- fused edge aggregation: warp per node, fp16, 8-way MLP -----
__global__ void __launch_bounds__(128) k_edge_agg(
        const uint4* __restrict__ feath,
        const float4* __restrict__ el4, const float4* __restrict__ er4,
        const int* __restrict__ rowptr, const int* __restrict__ csrc,
        const uint4* __restrict__ hprevh,
        const float4* __restrict__ bias4,
        uint4* __restrict__ houth) {
    int w = threadIdx.x >> 5;
    int n = blockIdx.x * 4 + w;
    int lane = threadIdx.x & 31;
    if (n >= NN) return;
    int head = lane >> 3;
    __shared__ int   ssrc[4][32];
    __shared__ float sw[4][32][4];
    int beg = rowptr[n], end = rowptr[n + 1];
    float4 erd = er4[n];
    float acc[8];
    #pragma unroll
    for (int i = 0; i < 8; i++) acc[i] = 0.f;
    float4 dl = make_float4(0.f, 0.f, 0.f, 0.f);

    #define ACCUM(fv, wgt) do {                                             \
        const __half2* _p = (const __half2*)&(fv);                          \
        _Pragma("unroll")                                                   \
        for (int _j = 0; _j < 4; _j++) {                                    \
            float2 _v = __half22float2(_p[_j]);                             \
            acc[2 * _j]     = fmaf(_v.x, (wgt), acc[2 * _j]);               \
            acc[2 * _j + 1] = fmaf(_v.y, (wgt), acc[2 * _j + 1]);           \
        } } while (0)

    for (int base = beg; base < end; base += 32) {
        int cnt = min(32, end - base);
        if (lane < cnt) {
            int s = csrc[base + lane];
            ssrc[w][lane] = s;
            float4 le = el4[s];
            float x0 = le.x + erd.x; x0 = x0 > 0.f ? x0 : NEG * x0;
            float x1 = le.y + erd.y; x1 = x1 > 0.f ? x1 : NEG * x1;
            float x2 = le.z + erd.z; x2 = x2 > 0.f ? x2 : NEG * x2;
            float x3 = le.w + erd.w; x3 = x3 > 0.f ? x3 : NEG * x3;
            float w0 = __expf(x0), w1 = __expf(x1), w2 = __expf(x2), w3 = __expf(x3);
            sw[w][lane][0] = w0; sw[w][lane][1] = w1;
            sw[w][lane][2] = w2; sw[w][lane][3] = w3;
            dl.x += w0; dl.y += w1; dl.z += w2; dl.w += w3;
        }
        __syncwarp();
        int e = 0;
        for (; e + 8 <= cnt; e += 8) {
            uint4 f0 = feath[(size_t)ssrc[w][e]     * 32 + lane];
            uint4 f1 = feath[(size_t)ssrc[w][e + 1] * 32 + lane];
            uint4 f2 = feath[(size_t)ssrc[w][e + 2] * 32 + lane];
            uint4 f3 = feath[(size_t)ssrc[w][e + 3] * 32 + lane];
            uint4 f4v = feath[(size_t)ssrc[w][e + 4] * 32 + lane];
            uint4 f5 = feath[(size_t)ssrc[w][e + 5] * 32 + lane];
            uint4 f6 = feath[(size_t)ssrc[w][e + 6] * 32 + lane];
            uint4 f7 = feath[(size_t)ssrc[w][e + 7] * 32 + lane];
            ACCUM(f0, sw[w][e][head]);     ACCUM(f1, sw[w][e + 1][head]);
            ACCUM(f2, sw[w][e + 2][head]); ACCUM(f3, sw[w][e + 3][head]);
            ACCUM(f4v, sw[w][e + 4][head]); ACCUM(f5, sw[w][e + 5][head]);
            ACCUM(f6, sw[w][e + 6][head]); ACCUM(f7, sw[w][e + 7][head]);
        }
        for (; e + 4 <= cnt; e += 4) {
            uint4 f0 = feath[(size_t)ssrc[w][e]     * 32 + lane];
            uint4 f1 = feath[(size_t)ssrc[w][e + 1] * 32 + lane];
            uint4 f2 = feath[(size_t)ssrc[w][e + 2] * 32 + lane];
            uint4 f3 = feath[(size_t)ssrc[w][e + 3] * 32 + lane];
            ACCUM(f0, sw[w][e][head]);     ACCUM(f1, sw[w][e + 1][head]);
            ACCUM(f2, sw[w][e + 2][head]); ACCUM(f3, sw[w][e + 3][head]);
        }
        for (; e < cnt; e++) {
            uint4 fv = feath[(size_t)ssrc[w][e] * 32 + lane];
            ACCUM(fv, sw[w][e][head]);
        }
        __syncwarp();
    }
    #undef ACCUM

    #pragma unroll
    for (int o = 16; o > 0; o >>= 1) {
        dl.x += __shfl_xor_sync(0xffffffffu, dl.x, o);
        dl.y += __shfl_xor_sync(0xffffffffu, dl.y, o);
        dl.z += __shfl_xor_sync(0xffffffffu, dl.z, o);
        dl.w += __shfl_xor_sync(0xffffffffu, dl.w, o);
    }
    float den = (head == 0) ? dl.x : (head == 1) ? dl.y : (head == 2) ? dl.z : dl.w;
    float inv = (end > beg) ? 1.f / den : 0.f;
    float4 b0 = bias4[lane * 2], b1 = bias4[lane * 2 + 1];
    float v[8];
    v[0] = acc[0] * inv + b0.x; v[1] = acc[1] * inv + b0.y;
    v[2] = acc[2] * inv + b0.z; v[3] = acc[3] * inv + b0.w;
    v[4] = acc[4] * inv + b1.x; v[5] = acc[5] * inv + b1.y;
    v[6] = acc[6] * inv + b1.z; v[7] = acc[7] * inv + b1.w;
    if (hprevh) {
        uint4 pv = hprevh[(size_t)n * 32 + lane];
        const __half2* pp = (const __half2*)&pv;
        #pragma unroll
        for (int j = 0; j < 4; j++) {
            float2 p = __half22float2(pp[j]);
            v[2 * j]     += p.x;
            v[2 * j + 1] += p.y;
        }
    }
    #pragma unroll
    for (int j = 0; j < 8; j++)
        v[j] = v[j] > 0.f ? v[j] : expm1f(v[j]);
    uint4 ob;
    ob.x = h2_as_u32(__floats2half2_rn(v[0], v[1]));
    ob.y = h2_as_u32(__floats2half2_rn(v[2], v[3]));
    ob.z = h2_as_u32(__floats2half2_rn(v[4], v[5]));
    ob.w = h2_as_u32(__floats2half2_rn(v[6], v[7]));
    houth[(size_t)n * 32 + lane] = ob;
}

// ---------------- layer-4 projection + el/er (merged, fp16 h) ----------------
__global__ void k_l4_proj(const __half* __restrict__ h, const float* __restrict__ W4,
                          const float* __restrict__ rW4,
                          const float* __restrict__ al4, const float* __restrict__ ar4,
                          float* __restrict__ f4, float* __restrict__ r4,
                          float* __restrict__ el, float* __restrict__ er) {
    int n = blockIdx.x * 8 + (threadIdx.x >> 5);
    int lane = threadIdx.x & 31;
    if (n >= NN) return;
    float acc[16];
    #pragma unroll
    for (int o = 0; o < 16; o++) acc[o] = 0.f;
    const __half* hr = h + (size_t)n * FD;
    #pragma unroll
    for (int k8 = 0; k8 < 8; k8++) {
        int k = k8 * 32 + lane;
        float hv = __half2float(hr[k]);
        #pragma unroll
        for (int o = 0; o < 8; o++) acc[o]     = fmaf(hv, W4[o * FD + k], acc[o]);
        #pragma unroll
        for (int o = 0; o < 8; o++) acc[8 + o] = fmaf(hv, rW4[o * FD + k], acc[8 + o]);
    }
    #pragma unroll
    for (int o = 0; o < 16; o++)
        #pragma unroll
        for (int off = 16; off > 0; off >>= 1)
            acc[o] += __shfl_xor_sync(0xffffffffu, acc[o], off);
    if (lane < 8) {
        f4[n * 8 + lane] = acc[lane];
        r4[n * 8 + lane] = acc[8 + lane];
    }
    if (lane < 4) {
        el[n * 4 + lane] = acc[2 * lane] * al4[2 * lane] +
                           acc[2 * lane + 1] * al4[2 * lane + 1];
        er[n * 4 + lane] = acc[2 * lane] * ar4[2 * lane] +
                           acc[2 * lane + 1] * ar4[2 * lane + 1];
    }
}

// ---------------- layer-4 edge agg + softmax + head-mean ---------------------
__global__ void k_l4_edge(const float* __restrict__ f4, const float* __restrict__ el,
                          const float* __restrict__ er, const int* __restrict__ rowptr,
                          const int* __restrict__ csrc, const float* __restrict__ r4,
                          const float* __restrict__ b4, float* __restrict__ out) {
    int n = blockIdx.x * 8 + (threadIdx.x >> 5);
    int lane = threadIdx.x & 31;
    if (n >= NN) return;
    int beg = rowptr[n], end = rowptr[n + 1];
    float4 erd = ((const float4*)er)[n];
    float acc[8] = {0, 0, 0, 0, 0, 0, 0, 0};
    float den[4] = {0, 0, 0, 0};
    for (int e = beg + lane; e < end; e += 32) {
        int s = csrc[e];
        float4 le = ((const float4*)el)[s];
        float x0 = le.x + erd.x; x0 = x0 > 0.f ? x0 : NEG * x0;
        float x1 = le.y + erd.y; x1 = x1 > 0.f ? x1 : NEG * x1;
        float x2 = le.z + erd.z; x2 = x2 > 0.f ? x2 : NEG * x2;
        float x3 = le.w + erd.w; x3 = x3 > 0.f ? x3 : NEG * x3;
        float w0 = __expf(x0), w1 = __expf(x1), w2 = __expf(x2), w3 = __expf(x3);
        den[0] += w0; den[1] += w1; den[2] += w2; den[3] += w3;
        float4 f0 = ((const float4*)f4)[s * 2];
        float4 f1 = ((const float4*)f4)[s * 2 + 1];
        acc[0] = fmaf(f0.x, w0, acc[0]);  acc[1] = fmaf(f0.y, w0, acc[1]);
        acc[2] = fmaf(f0.z, w1, acc[2]);  acc[3] = fmaf(f0.w, w1, acc[3]);
        acc[4] = fmaf(f1.x, w2, acc[4]);  acc[5] = fmaf(f1.y, w2, acc[5]);
        acc[6] = fmaf(f1.z, w3, acc[6]);  acc[7] = fmaf(f1.w, w3, acc[7]);
    }
    #pragma unroll
    for (int off = 16; off > 0; off >>= 1) {
        #pragma unroll
        for (int o = 0; o < 8; o++) acc[o] += __shfl_xor_sync(0xffffffffu, acc[o], off);
        #pragma unroll
        for (int h = 0; h < 4; h++) den[h] += __shfl_xor_sync(0xffffffffu, den[h], off);
    }
    if (lane == 0) {
        bool has = end > beg;
        float o0 = 0.f, o1 = 0.f;
        #pragma unroll
        for (int h = 0; h < 4; h++) {
            float r0 = has ? acc[2 * h] / den[h] : 0.f;
            float r1 = has ? acc[2 * h + 1] / den[h] : 0.f;
            r0 += r4[n * 8 + 2 * h] + b4[2 * h];
            r1 += r4[n * 8 + 2 * h + 1] + b4[2 * h + 1];
            float m = fmaxf(r0, r1);
            float e0 = expf(r0 - m), e1 = expf(r1 - m);
            float s = e0 + e1;
            o0 += e0 / s;
            o1 += e1 / s;
        }
        out[n * 2 + 0] = o0 * 0.25f;
        out[n * 2 + 1] = o1 * 0.25f;
    }
}

// ---------------- host launcher ----------------------------------------------
extern "C" void kernel_launch(void* const* d_in, const int* in_sizes, int n_in,
                              void* d_out, int out_size) {
    const float* x     = (const float*)d_in[0];
    const int*   src   = (const int*)  d_in[1];
    const int*   dst   = (const int*)  d_in[2];
    const float* W1    = (const float*)d_in[3];
    const float* al1   = (const float*)d_in[4];
    const float* ar1   = (const float*)d_in[5];
    const float* b1    = (const float*)d_in[6];
    const float* W2    = (const float*)d_in[7];
    const float* al2   = (const float*)d_in[8];
    const float* ar2   = (const float*)d_in[9];
    const float* b2    = (const float*)d_in[10];
    const float* W3    = (const float*)d_in[11];
    const float* al3   = (const float*)d_in[12];
    const float* ar3   = (const float*)d_in[13];
    const float* b3    = (const float*)d_in[14];
    const float* W4    = (const float*)d_in[15];
    const float* al4   = (const float*)d_in[16];
    const float* ar4   = (const float*)d_in[17];
    const float* b4    = (const float*)d_in[18];
    const float* resW4 = (const float*)d_in[19];
    float* out = (float*)d_out;
    const int E = in_sizes[1];

    __half *feath, *xh, *hAh, *hBh, *W1h, *W2h, *W3h;
    float *el, *er, *f4, *r4;
    int *cnt, *rowptr, *cur, *csrc;
    cudaGetSymbolAddress((void**)&feath,  g_feath);
    cudaGetSymbolAddress((void**)&xh,     g_xh);
    cudaGetSymbolAddress((void**)&hAh,    g_hAh);
    cudaGetSymbolAddress((void**)&hBh,    g_hBh);
    cudaGetSymbolAddress((void**)&W1h,    g_W1h);
    cudaGetSymbolAddress((void**)&W2h,    g_W2h);
    cudaGetSymbolAddress((void**)&W3h,    g_W3h);
    cudaGetSymbolAddress((void**)&el,     g_el);
    cudaGetSymbolAddress((void**)&er,     g_er);
    cudaGetSymbolAddress((void**)&f4,     g_f4);
    cudaGetSymbolAddress((void**)&r4,     g_r4);
    cudaGetSymbolAddress((void**)&cnt,    g_cnt);
    cudaGetSymbolAddress((void**)&rowptr, g_rowptr);
    cudaGetSymbolAddress((void**)&cur,    g_cur);
    cudaGetSymbolAddress((void**)&csrc,   g_csrc);

    cudaFuncSetAttribute(k_gemm_fp16,
                         cudaFuncAttributeMaxDynamicSharedMemorySize, GEMM_SMEM);

    // ---- converts + cnt zeroing ----
    const int xn4 = NN * 128 / 4;
    k_cvtAll<<<(xn4 + 255) / 256, 256>>>((const float4*)x, (uint2*)xh, xn4,
                                         (const float4*)W1, (uint2*)W1h,
                                         (const float4*)W2, (uint2*)W2h,
                                         (const float4*)W3, (uint2*)W3h, cnt);

    // ---- CSR by dst ----
    k_histo<<<1024, 256>>>(dst, cnt, E);
    k_scan_part<<<NB, 1024>>>(cnt);
    k_scan_final<<<NB, 1024>>>(cnt, rowptr, cur);
    k_scatter<<<1024, 256>>>(src, dst, cur, csrc, E);

    dim3 gemm_grid(FD / BN, (NN + BM - 1) / BM);   // (2, 391)
    const int agg_grid = (NN + 3) / 4;

    // ---- layer 1 ----
    k_gemm_fp16<<<gemm_grid, 256, GEMM_SMEM>>>(xh, W1h, feath, al1, ar1, el, er, NN, 128);
    k_edge_agg<<<agg_grid, 128>>>((const uint4*)feath, (const float4*)el,
                                  (const float4*)er, rowptr, csrc, nullptr,
                                  (const float4*)b1, (uint4*)hAh);

    // ---- layer 2 ----
    k_gemm_fp16<<<gemm_grid, 256, GEMM_SMEM>>>(hAh, W2h, feath, al2, ar2, el, er, NN, FD);
    k_edge_agg<<<agg_grid, 128>>>((const uint4*)feath, (const float4*)el,
                                  (const float4*)er, rowptr, csrc,
                                  (const uint4*)hAh, (const float4*)b2, (uint4*)hBh);

    // ---- layer 3 ----
    k_gemm_fp16<<<gemm_grid, 256, GEMM_SMEM>>>(hBh, W3h, feath, al3, ar3, el, er, NN, FD);
    k_edge_agg<<<agg_grid, 128>>>((const uint4*)feath, (const float4*)el,
                                  (const float4*)er, rowptr, csrc,
                                  (const uint4*)hBh, (const float4*)b3, (uint4*)hAh);

    // ---- layer 4 ----
    k_l4_proj<<<(NN + 7) / 8, 256>>>(hAh, W4, resW4, al4, ar4, f4, r4, el, er);
    k_l4_edge<<<(NN + 7) / 8, 256>>>(f4, el, er, rowptr, csrc, r4, b4, out);
}